// round 5
// baseline (speedup 1.0000x reference)
#include <cuda_runtime.h>

// Problem constants
#define E_DIM   1024
#define N_HEADS 16
#define HDIM    64
#define NB      4
#define SEQ     2048
#define BH_TOT  (NB * N_HEADS)   // 64
#define M_ROWS  (NB * SEQ)       // 8192

// Scratch (device globals: no allocation allowed)
__device__ float g_q[BH_TOT * SEQ * HDIM];   // [B,H,T,D], pre-scaled by D^-0.5
__device__ float g_k[BH_TOT * SEQ * HDIM];
__device__ float g_v[BH_TOT * SEQ * HDIM];
__device__ float g_ctx[M_ROWS * E_DIM];      // [B,T,H*D]

// ---- packed f32x2 helpers (sm_103a FFMA2 path, PTX-only) --------------------
__device__ __forceinline__ void ffma2(unsigned long long& d,
                                      unsigned long long a,
                                      unsigned long long b) {
    asm("fma.rn.f32x2 %0, %1, %2, %0;" : "+l"(d) : "l"(a), "l"(b));
}
__device__ __forceinline__ void fmul2(unsigned long long& d,
                                      unsigned long long a,
                                      unsigned long long b) {
    asm("mul.rn.f32x2 %0, %1, %2;" : "=l"(d) : "l"(a), "l"(b));
}
__device__ __forceinline__ unsigned long long pack2(float lo, float hi) {
    unsigned long long r;
    asm("mov.b64 %0, {%1, %2};" : "=l"(r) : "f"(lo), "f"(hi));
    return r;
}
__device__ __forceinline__ float2 unpack2(unsigned long long v) {
    float2 r;
    asm("mov.b64 {%0, %1}, %2;" : "=f"(r.x), "=f"(r.y) : "l"(v));
    return r;
}

// ---------------------------------------------------------------------------
// NT GEMM: C[m,n] = sum_k A[m,k] * W[n,k] + bias[n]
// 128x128 tile, BK=16, 256 threads, 8x8 per thread via 32 FFMA2/k-step.
// A tile stored DUPLICATED in smem: As2[k][2m]=As2[k][2m+1]=A so the broadcast
// operand loads as ready (a,a) f32x2 pairs. B pairs naturally along n.
// mode 0: store to C [M,N].  mode 1: scatter QKV into g_q/g_k/g_v (q *= 0.125).
// A == nullptr means "read from g_ctx".
// ---------------------------------------------------------------------------
__global__ __launch_bounds__(256) void gemm_nt(
    const float* __restrict__ A, const float* __restrict__ W,
    const float* __restrict__ bias, float* __restrict__ C,
    int K, int N, int mode)
{
    __shared__ float As2[16][264];   // dup'd: [k][2*m(+pad)]
    __shared__ float Bs[16][132];    // [k][n]

    const float* Ain = A ? A : g_ctx;

    int t  = threadIdx.x;
    int ty = t >> 4;          // 0..15
    int tx = t & 15;          // 0..15
    int lrow = t >> 1;        // 0..127
    int lcol = (t & 1) << 3;  // 0 or 8

    const float* Ap = Ain + (size_t)(blockIdx.y * 128 + lrow) * K + lcol;
    const float* Wp = W   + (size_t)(blockIdx.x * 128 + lrow) * K + lcol;

    unsigned long long acc[8][4];
#pragma unroll
    for (int i = 0; i < 8; i++)
#pragma unroll
        for (int j = 0; j < 4; j++) acc[i][j] = 0ULL;

    for (int k0 = 0; k0 < K; k0 += 16) {
        float4 a0 = *(const float4*)(Ap + k0);
        float4 a1 = *(const float4*)(Ap + k0 + 4);
        float4 b0 = *(const float4*)(Wp + k0);
        float4 b1 = *(const float4*)(Wp + k0 + 4);
        __syncthreads();  // previous tile's compute done before overwrite
        *(float2*)&As2[lcol + 0][2 * lrow] = make_float2(a0.x, a0.x);
        *(float2*)&As2[lcol + 1][2 * lrow] = make_float2(a0.y, a0.y);
        *(float2*)&As2[lcol + 2][2 * lrow] = make_float2(a0.z, a0.z);
        *(float2*)&As2[lcol + 3][2 * lrow] = make_float2(a0.w, a0.w);
        *(float2*)&As2[lcol + 4][2 * lrow] = make_float2(a1.x, a1.x);
        *(float2*)&As2[lcol + 5][2 * lrow] = make_float2(a1.y, a1.y);
        *(float2*)&As2[lcol + 6][2 * lrow] = make_float2(a1.z, a1.z);
        *(float2*)&As2[lcol + 7][2 * lrow] = make_float2(a1.w, a1.w);
        Bs[lcol + 0][lrow] = b0.x; Bs[lcol + 1][lrow] = b0.y;
        Bs[lcol + 2][lrow] = b0.z; Bs[lcol + 3][lrow] = b0.w;
        Bs[lcol + 4][lrow] = b1.x; Bs[lcol + 5][lrow] = b1.y;
        Bs[lcol + 6][lrow] = b1.z; Bs[lcol + 7][lrow] = b1.w;
        __syncthreads();
#pragma unroll
        for (int k = 0; k < 16; k++) {
            // 8 dup'd a-pairs (broadcast within warp: 2 distinct addrs)
            ulonglong2 aa0 = *(const ulonglong2*)&As2[k][(ty * 4) * 2];
            ulonglong2 aa1 = *(const ulonglong2*)&As2[k][(ty * 4) * 2 + 4];
            ulonglong2 aa2 = *(const ulonglong2*)&As2[k][(64 + ty * 4) * 2];
            ulonglong2 aa3 = *(const ulonglong2*)&As2[k][(64 + ty * 4) * 2 + 4];
            // 8 b values as 4 natural pairs
            ulonglong2 bL = *(const ulonglong2*)&Bs[k][tx * 4];
            ulonglong2 bH = *(const ulonglong2*)&Bs[k][64 + tx * 4];

            ffma2(acc[0][0], aa0.x, bL.x); ffma2(acc[0][1], aa0.x, bL.y);
            ffma2(acc[0][2], aa0.x, bH.x); ffma2(acc[0][3], aa0.x, bH.y);
            ffma2(acc[1][0], aa0.y, bL.x); ffma2(acc[1][1], aa0.y, bL.y);
            ffma2(acc[1][2], aa0.y, bH.x); ffma2(acc[1][3], aa0.y, bH.y);
            ffma2(acc[2][0], aa1.x, bL.x); ffma2(acc[2][1], aa1.x, bL.y);
            ffma2(acc[2][2], aa1.x, bH.x); ffma2(acc[2][3], aa1.x, bH.y);
            ffma2(acc[3][0], aa1.y, bL.x); ffma2(acc[3][1], aa1.y, bL.y);
            ffma2(acc[3][2], aa1.y, bH.x); ffma2(acc[3][3], aa1.y, bH.y);
            ffma2(acc[4][0], aa2.x, bL.x); ffma2(acc[4][1], aa2.x, bL.y);
            ffma2(acc[4][2], aa2.x, bH.x); ffma2(acc[4][3], aa2.x, bH.y);
            ffma2(acc[5][0], aa2.y, bL.x); ffma2(acc[5][1], aa2.y, bL.y);
            ffma2(acc[5][2], aa2.y, bH.x); ffma2(acc[5][3], aa2.y, bH.y);
            ffma2(acc[6][0], aa3.x, bL.x); ffma2(acc[6][1], aa3.x, bL.y);
            ffma2(acc[6][2], aa3.x, bH.x); ffma2(acc[6][3], aa3.x, bH.y);
            ffma2(acc[7][0], aa3.y, bL.x); ffma2(acc[7][1], aa3.y, bL.y);
            ffma2(acc[7][2], aa3.y, bH.x); ffma2(acc[7][3], aa3.y, bH.y);
        }
    }

    int rbase = blockIdx.y * 128;
    int cbase = blockIdx.x * 128;
#pragma unroll
    for (int i = 0; i < 8; i++) {
        int m = rbase + ((i < 4) ? (ty * 4 + i) : (64 + ty * 4 + (i - 4)));
#pragma unroll
        for (int jj = 0; jj < 4; jj++) {
            int n = cbase + ((jj < 2) ? (tx * 4 + 2 * jj)
                                      : (64 + tx * 4 + 2 * (jj - 2)));
            float2 p = unpack2(acc[i][jj]);
            float v0 = p.x + bias[n];
            float v1 = p.y + bias[n + 1];
            if (mode == 0) {
                *(float2*)&C[(size_t)m * N + n] = make_float2(v0, v1);
            } else {
                int part = n >> 10;       // 0:q 1:k 2:v  (n even; pair stays inside)
                int r    = n & 1023;
                int h    = r >> 6;
                int d    = r & 63;
                int b    = m >> 11;
                int tt   = m & 2047;
                int idx  = ((b * N_HEADS + h) * SEQ + tt) * HDIM + d;
                if (part == 0)
                    *(float2*)&g_q[idx] = make_float2(v0 * 0.125f, v1 * 0.125f);
                else if (part == 1)
                    *(float2*)&g_k[idx] = make_float2(v0, v1);
                else
                    *(float2*)&g_v[idx] = make_float2(v0, v1);
            }
        }
    }
}

// ---------------------------------------------------------------------------
// Flash attention, fp32 + FFMA2. One block per (64-row q-tile, bh).
// QK^T: pack over k (dot-product pairs, horizontal add).
// PV:   P written DUPLICATED by the softmax phase (Sd), V pairs over j.
// ---------------------------------------------------------------------------
#define PADW 68
#define SDW  136
#define ATTN_FLOATS (4 * 64 * PADW + 64 * SDW + 3 * 64)
#define ATTN_SMEM_BYTES (ATTN_FLOATS * 4)

__global__ __launch_bounds__(256) void attn_kernel()
{
    extern __shared__ float sm[];
    float* Qs   = sm;                  // [64][PADW]
    float* Ks   = Qs + 64 * PADW;
    float* Vs   = Ks + 64 * PADW;
    float* Ss   = Vs + 64 * PADW;      // raw scores [64][PADW]
    float* Sd   = Ss + 64 * PADW;      // dup'd exp(P) [64][SDW]
    float* rowm = Sd + 64 * SDW;       // [64]
    float* rowl = rowm + 64;
    float* rowa = rowl + 64;

    int t  = threadIdx.x;
    int ty = t >> 4, tx = t & 15;
    int bh = blockIdx.y;
    int q0 = blockIdx.x * 64;

    // Load Q tile (64x64)
    const float* qbase = g_q + (size_t)(bh * SEQ + q0) * HDIM;
#pragma unroll
    for (int q = 0; q < 4; q++) {
        int id = t + 256 * q;
        int r  = id >> 4;
        int c  = (id & 15) << 2;
        *(float4*)&Qs[r * PADW + c] = *(const float4*)(qbase + r * HDIM + c);
    }
    if (t < 64) { rowm[t] = -1e30f; rowl[t] = 0.f; }

    unsigned long long o2[4][2];       // o[i][0..1]=pair(j0,j1), [i][1]=(j2,j3)
#pragma unroll
    for (int i = 0; i < 4; i++) { o2[i][0] = 0ULL; o2[i][1] = 0ULL; }

    for (int jt = 0; jt < SEQ / 64; jt++) {
        __syncthreads();  // prev PV done before K/V (and Ss) overwrite
        const float* kbase = g_k + (size_t)(bh * SEQ + jt * 64) * HDIM;
        const float* vbase = g_v + (size_t)(bh * SEQ + jt * 64) * HDIM;
#pragma unroll
        for (int q = 0; q < 4; q++) {
            int id = t + 256 * q;
            int r  = id >> 4;
            int c  = (id & 15) << 2;
            *(float4*)&Ks[r * PADW + c] = *(const float4*)(kbase + r * HDIM + c);
            *(float4*)&Vs[r * PADW + c] = *(const float4*)(vbase + r * HDIM + c);
        }
        __syncthreads();

        // S = Q @ K^T, packed over k
        unsigned long long s2[4][4];
#pragma unroll
        for (int i = 0; i < 4; i++)
#pragma unroll
            for (int j = 0; j < 4; j++) s2[i][j] = 0ULL;

#pragma unroll 4
        for (int k = 0; k < 64; k += 4) {
            ulonglong2 q2[4], k2[4];
#pragma unroll
            for (int i = 0; i < 4; i++)
                q2[i] = *(const ulonglong2*)&Qs[(ty * 4 + i) * PADW + k];
#pragma unroll
            for (int j = 0; j < 4; j++)
                k2[j] = *(const ulonglong2*)&Ks[(tx * 4 + j) * PADW + k];
#pragma unroll
            for (int i = 0; i < 4; i++)
#pragma unroll
                for (int j = 0; j < 4; j++) {
                    ffma2(s2[i][j], q2[i].x, k2[j].x);
                    ffma2(s2[i][j], q2[i].y, k2[j].y);
                }
        }
#pragma unroll
        for (int i = 0; i < 4; i++) {
            float2 u0 = unpack2(s2[i][0]);
            float2 u1 = unpack2(s2[i][1]);
            float2 u2 = unpack2(s2[i][2]);
            float2 u3 = unpack2(s2[i][3]);
            *(float4*)&Ss[(ty * 4 + i) * PADW + tx * 4] =
                make_float4(u0.x + u0.y, u1.x + u1.y, u2.x + u2.y, u3.x + u3.y);
        }
        __syncthreads();

        // Online softmax: 4 threads per row, 16 cols each; writes dup'd exp to Sd
        {
            int r = t >> 2, p = t & 3;
            const float* srow = &Ss[r * PADW + p * 16];
            float* drow = &Sd[r * SDW + p * 32];
            float mx = srow[0];
#pragma unroll
            for (int c = 1; c < 16; c++) mx = fmaxf(mx, srow[c]);
            mx = fmaxf(mx, __shfl_xor_sync(0xffffffffu, mx, 1));
            mx = fmaxf(mx, __shfl_xor_sync(0xffffffffu, mx, 2));
            float m_old = rowm[r];
            float m_new = fmaxf(m_old, mx);
            float sum = 0.f;
#pragma unroll
            for (int c = 0; c < 16; c++) {
                float e = __expf(srow[c] - m_new);
                *(float2*)&drow[2 * c] = make_float2(e, e);
                sum += e;
            }
            sum += __shfl_xor_sync(0xffffffffu, sum, 1);
            sum += __shfl_xor_sync(0xffffffffu, sum, 2);
            if (p == 0) {
                float alpha = __expf(m_old - m_new);  // 0 on first tile
                rowa[r] = alpha;
                rowm[r] = m_new;
                rowl[r] = rowl[r] * alpha + sum;
            }
        }
        __syncthreads();

        // O = O*alpha + P @ V  (P dup'd pairs from Sd, V natural pairs)
#pragma unroll
        for (int i = 0; i < 4; i++) {
            float a = rowa[ty * 4 + i];
            unsigned long long al = pack2(a, a);
            fmul2(o2[i][0], o2[i][0], al);
            fmul2(o2[i][1], o2[i][1], al);
        }

#pragma unroll 4
        for (int k = 0; k < 64; k += 4) {
            ulonglong2 pA[4], pB[4], v2[4];
#pragma unroll
            for (int i = 0; i < 4; i++) {
                pA[i] = *(const ulonglong2*)&Sd[(ty * 4 + i) * SDW + 2 * k];
                pB[i] = *(const ulonglong2*)&Sd[(ty * 4 + i) * SDW + 2 * k + 4];
            }
#pragma unroll
            for (int kk = 0; kk < 4; kk++)
                v2[kk] = *(const ulonglong2*)&Vs[(k + kk) * PADW + tx * 4];
#pragma unroll
            for (int i = 0; i < 4; i++) {
                ffma2(o2[i][0], pA[i].x, v2[0].x); ffma2(o2[i][1], pA[i].x, v2[0].y);
                ffma2(o2[i][0], pA[i].y, v2[1].x); ffma2(o2[i][1], pA[i].y, v2[1].y);
                ffma2(o2[i][0], pB[i].x, v2[2].x); ffma2(o2[i][1], pB[i].x, v2[2].y);
                ffma2(o2[i][0], pB[i].y, v2[3].x); ffma2(o2[i][1], pB[i].y, v2[3].y);
            }
        }
    }

    // Normalize and write ctx in [B,T,H,D] (== [B,T,E]) layout
    int b = bh >> 4, h = bh & 15;
#pragma unroll
    for (int i = 0; i < 4; i++) {
        float inv = 1.0f / rowl[ty * 4 + i];
        int tt = q0 + ty * 4 + i;
        float2 uL = unpack2(o2[i][0]);
        float2 uH = unpack2(o2[i][1]);
        float* dst = g_ctx + ((size_t)(b * SEQ + tt) * N_HEADS + h) * HDIM + tx * 4;
        *(float4*)dst = make_float4(uL.x * inv, uL.y * inv,
                                    uH.x * inv, uH.y * inv);
    }
}

// ---------------------------------------------------------------------------
extern "C" void kernel_launch(void* const* d_in, const int* in_sizes, int n_in,
                              void* d_out, int out_size)
{
    const float* query = (const float*)d_in[0];   // [4,2048,1024]
    const float* in_w  = (const float*)d_in[1];   // [3072,1024]
    const float* in_b  = (const float*)d_in[2];   // [3072]
    const float* out_w = (const float*)d_in[3];   // [1024,1024]
    const float* out_b = (const float*)d_in[4];   // [1024]
    float* out = (float*)d_out;                   // [4,2048,1024]

    cudaFuncSetAttribute(attn_kernel,
                         cudaFuncAttributeMaxDynamicSharedMemorySize,
                         ATTN_SMEM_BYTES);

    // 1) QKV projection + scatter to [B,H,T,D] (q scaled)
    gemm_nt<<<dim3(3 * E_DIM / 128, M_ROWS / 128), 256>>>(
        query, in_w, in_b, nullptr, E_DIM, 3 * E_DIM, 1);

    // 2) Flash attention -> g_ctx
    attn_kernel<<<dim3(SEQ / 64, BH_TOT), 256, ATTN_SMEM_BYTES>>>();

    // 3) Output projection -> d_out
    gemm_nt<<<dim3(E_DIM / 128, M_ROWS / 128), 256>>>(
        nullptr, out_w, out_b, out, E_DIM, E_DIM, 0);
}

// round 7
// speedup vs baseline: 1.4070x; 1.4070x over previous
#include <cuda_runtime.h>
#include <cstdint>

// Problem constants
#define E_DIM   1024
#define N_HEADS 16
#define HDIM    64
#define NB      4
#define SEQ     2048
#define BH_TOT  (NB * N_HEADS)   // 64
#define M_ROWS  (NB * SEQ)       // 8192

// Scratch (device globals: no allocation allowed)
__device__ float g_q[BH_TOT * SEQ * HDIM];   // [B,H,T,D], pre-scaled by D^-0.5
__device__ float g_k[BH_TOT * SEQ * HDIM];
__device__ float g_v[BH_TOT * SEQ * HDIM];
__device__ float g_ctx[M_ROWS * E_DIM];      // [B,T,H*D]

// ---- helpers ---------------------------------------------------------------
__device__ __forceinline__ uint32_t smem_u32(const void* p) {
    uint32_t a;
    asm("{ .reg .u64 t; cvta.to.shared.u64 t, %1; cvt.u32.u64 %0, t; }"
        : "=r"(a) : "l"(p));
    return a;
}
// pack two f32 -> bf16x2 (lo element in low 16 bits)
__device__ __forceinline__ uint32_t bf2(float e0, float e1) {
    uint32_t r;
    asm("cvt.rn.bf16x2.f32 %0, %1, %2;" : "=r"(r) : "f"(e1), "f"(e0));
    return r;
}
__device__ __forceinline__ float bf_lo_f32(uint32_t p) {
    return __uint_as_float(p << 16);
}
__device__ __forceinline__ float bf_hi_f32(uint32_t p) {
    return __uint_as_float(p & 0xffff0000u);
}

#define LDSM_X4(r0, r1, r2, r3, addr)                                        \
    asm volatile("ldmatrix.sync.aligned.m8n8.x4.shared.b16 "                 \
                 "{%0, %1, %2, %3}, [%4];"                                   \
                 : "=r"(r0), "=r"(r1), "=r"(r2), "=r"(r3) : "r"(addr))

#define MMA_BF16(c, a, b)                                                    \
    asm volatile("mma.sync.aligned.m16n8k16.row.col.f32.bf16.bf16.f32 "      \
                 "{%0, %1, %2, %3}, {%4, %5, %6, %7}, {%8, %9}, "            \
                 "{%0, %1, %2, %3};"                                         \
                 : "+f"((c)[0]), "+f"((c)[1]), "+f"((c)[2]), "+f"((c)[3])    \
                 : "r"((a)[0]), "r"((a)[1]), "r"((a)[2]), "r"((a)[3]),       \
                   "r"((b)[0]), "r"((b)[1]))

// ===========================================================================
// bf16x3 tensor-core NT GEMM: C[m,n] = sum_k A[m,k]*W[n,k] + bias[n]
// fp32 emulated as bf16 hi/lo split; acc += Ah*Bh + Ah*Bl + Al*Bh (fp32 acc).
// 128x128 CTA tile, BK=32, 256 threads, 8 warps in 2(m) x 4(n); each warp
// owns 64x32 of C. Fragments via ldmatrix from hi/lo bf16 smem planes
// (row stride 40 bf16 = 80B -> conflict-free ldmatrix).
// mode 0: C[M,N].  mode 1: QKV scatter (q *= 0.125).  A==nullptr -> g_ctx.
// ===========================================================================
#define SROW 40   // bf16 elems per smem row (32 data + 8 pad)

__global__ __launch_bounds__(256) void gemm_mma(
    const float* __restrict__ A, const float* __restrict__ W,
    const float* __restrict__ bias, float* __restrict__ C,
    int K, int N, int mode)
{
    __shared__ uint16_t As_hi[128 * SROW];
    __shared__ uint16_t As_lo[128 * SROW];
    __shared__ uint16_t Ws_hi[128 * SROW];
    __shared__ uint16_t Ws_lo[128 * SROW];

    const float* Ain = A ? A : g_ctx;

    int t    = threadIdx.x;
    int lane = t & 31;
    int wid  = t >> 5;
    int wm   = wid >> 2;          // 0..1  (64 rows each)
    int wn   = wid & 3;           // 0..3  (32 cols each)
    int gid  = lane >> 2;         // mma group id
    int tig  = lane & 3;

    int rbase = blockIdx.y * 128;
    int cbase = blockIdx.x * 128;

    // per-lane ldmatrix offset (bytes): row (lane&15), k-half (lane>>4)*8 elems
    uint32_t lm_off = (uint32_t)((lane & 15) * SROW + ((lane >> 4) << 3)) * 2;
    uint32_t aHiB = smem_u32(As_hi) + (uint32_t)(wm * 64 * SROW * 2) + lm_off;
    uint32_t aLoB = smem_u32(As_lo) + (uint32_t)(wm * 64 * SROW * 2) + lm_off;
    uint32_t bHiB = smem_u32(Ws_hi) + (uint32_t)(wn * 32 * SROW * 2) + lm_off;
    uint32_t bLoB = smem_u32(Ws_lo) + (uint32_t)(wn * 32 * SROW * 2) + lm_off;

    float acc[4][4][4];
#pragma unroll
    for (int i = 0; i < 4; i++)
#pragma unroll
        for (int j = 0; j < 4; j++)
#pragma unroll
            for (int r = 0; r < 4; r++) acc[i][j][r] = 0.f;

    const int nch = K / 32;
    for (int ch = 0; ch < nch; ch++) {
        int k0 = ch * 32;
        __syncthreads();  // previous compute done before overwrite
        // load 128x32 fp32 of A and W, split to bf16 hi/lo planes
#pragma unroll
        for (int q = 0; q < 4; q++) {
            int idx = t + 256 * q;          // 0..1023 float4 slots
            int row = idx >> 3;
            int c4  = (idx & 7) << 2;
            uint32_t so = (uint32_t)(row * SROW + c4);

            float4 a = *(const float4*)(Ain + (size_t)(rbase + row) * K + k0 + c4);
            uint32_t h01 = bf2(a.x, a.y), h23 = bf2(a.z, a.w);
            uint32_t l01 = bf2(a.x - bf_lo_f32(h01), a.y - bf_hi_f32(h01));
            uint32_t l23 = bf2(a.z - bf_lo_f32(h23), a.w - bf_hi_f32(h23));
            *(uint2*)&As_hi[so] = make_uint2(h01, h23);
            *(uint2*)&As_lo[so] = make_uint2(l01, l23);

            float4 b = *(const float4*)(W + (size_t)(cbase + row) * K + k0 + c4);
            uint32_t wh01 = bf2(b.x, b.y), wh23 = bf2(b.z, b.w);
            uint32_t wl01 = bf2(b.x - bf_lo_f32(wh01), b.y - bf_hi_f32(wh01));
            uint32_t wl23 = bf2(b.z - bf_lo_f32(wh23), b.w - bf_hi_f32(wh23));
            *(uint2*)&Ws_hi[so] = make_uint2(wh01, wh23);
            *(uint2*)&Ws_lo[so] = make_uint2(wl01, wl23);
        }
        __syncthreads();

#pragma unroll
        for (int kk = 0; kk < 2; kk++) {     // two k16 steps per chunk
            uint32_t kb = (uint32_t)(kk * 16 * 2);
            uint32_t Ah[4][4], Al[4][4], Bh[4][2], Bl[4][2];
#pragma unroll
            for (int mt = 0; mt < 4; mt++) {
                uint32_t off = kb + (uint32_t)(mt * 16 * SROW * 2);
                LDSM_X4(Ah[mt][0], Ah[mt][1], Ah[mt][2], Ah[mt][3], aHiB + off);
                LDSM_X4(Al[mt][0], Al[mt][1], Al[mt][2], Al[mt][3], aLoB + off);
            }
#pragma unroll
            for (int nt2 = 0; nt2 < 2; nt2++) {   // 16 n-rows per ldsm.x4
                uint32_t off = kb + (uint32_t)(nt2 * 16 * SROW * 2);
                uint32_t r0, r1, r2, r3;
                LDSM_X4(r0, r1, r2, r3, bHiB + off);
                Bh[nt2 * 2][0] = r0; Bh[nt2 * 2 + 1][0] = r1;
                Bh[nt2 * 2][1] = r2; Bh[nt2 * 2 + 1][1] = r3;
                LDSM_X4(r0, r1, r2, r3, bLoB + off);
                Bl[nt2 * 2][0] = r0; Bl[nt2 * 2 + 1][0] = r1;
                Bl[nt2 * 2][1] = r2; Bl[nt2 * 2 + 1][1] = r3;
            }
#pragma unroll
            for (int mt = 0; mt < 4; mt++)
#pragma unroll
                for (int nt = 0; nt < 4; nt++) {
                    MMA_BF16(acc[mt][nt], Ah[mt], Bh[nt]);
                    MMA_BF16(acc[mt][nt], Ah[mt], Bl[nt]);
                    MMA_BF16(acc[mt][nt], Al[mt], Bh[nt]);
                }
        }
    }

    // Epilogue: thread owns rows (gid, gid+8), col pair 2*tig per (mt,nt)
#pragma unroll
    for (int mt = 0; mt < 4; mt++) {
#pragma unroll
        for (int nt = 0; nt < 4; nt++) {
            int n = cbase + wn * 32 + nt * 8 + 2 * tig;
            float bz0 = bias[n], bz1 = bias[n + 1];
#pragma unroll
            for (int half = 0; half < 2; half++) {
                int m = rbase + wm * 64 + mt * 16 + gid + half * 8;
                float v0 = acc[mt][nt][half * 2]     + bz0;
                float v1 = acc[mt][nt][half * 2 + 1] + bz1;
                if (mode == 0) {
                    *(float2*)&C[(size_t)m * N + n] = make_float2(v0, v1);
                } else {
                    int part = n >> 10;     // 0:q 1:k 2:v  (n even -> pair inside)
                    int rr   = n & 1023;
                    int h    = rr >> 6;
                    int d    = rr & 63;
                    int b    = m >> 11;
                    int tt   = m & 2047;
                    int idx  = ((b * N_HEADS + h) * SEQ + tt) * HDIM + d;
                    if (part == 0)
                        *(float2*)&g_q[idx] = make_float2(v0 * 0.125f, v1 * 0.125f);
                    else if (part == 1)
                        *(float2*)&g_k[idx] = make_float2(v0, v1);
                    else
                        *(float2*)&g_v[idx] = make_float2(v0, v1);
                }
            }
        }
    }
}

// ---------------------------------------------------------------------------
// Flash attention, fp32 scalar (known good).
// ---------------------------------------------------------------------------
#define PADW 68
#define ATTN_SMEM_BYTES ((4 * 64 * PADW + 3 * 64) * 4)

__global__ __launch_bounds__(256) void attn_kernel()
{
    extern __shared__ float sm[];
    float* Qs   = sm;                  // [64][PADW]
    float* Ks   = Qs + 64 * PADW;
    float* Vs   = Ks + 64 * PADW;
    float* Ss   = Vs + 64 * PADW;
    float* rowm = Ss + 64 * PADW;      // [64]
    float* rowl = rowm + 64;
    float* rowa = rowl + 64;

    int t  = threadIdx.x;
    int ty = t >> 4, tx = t & 15;
    int bh = blockIdx.y;
    int q0 = blockIdx.x * 64;

    const float* qbase = g_q + (size_t)(bh * SEQ + q0) * HDIM;
#pragma unroll
    for (int q = 0; q < 4; q++) {
        int id = t + 256 * q;
        int r  = id >> 4;
        int c  = (id & 15) << 2;
        *(float4*)&Qs[r * PADW + c] = *(const float4*)(qbase + r * HDIM + c);
    }
    if (t < 64) { rowm[t] = -1e30f; rowl[t] = 0.f; }

    float o[4][4];
#pragma unroll
    for (int i = 0; i < 4; i++)
#pragma unroll
        for (int j = 0; j < 4; j++) o[i][j] = 0.f;

    for (int jt = 0; jt < SEQ / 64; jt++) {
        __syncthreads();
        const float* kbase = g_k + (size_t)(bh * SEQ + jt * 64) * HDIM;
        const float* vbase = g_v + (size_t)(bh * SEQ + jt * 64) * HDIM;
#pragma unroll
        for (int q = 0; q < 4; q++) {
            int id = t + 256 * q;
            int r  = id >> 4;
            int c  = (id & 15) << 2;
            *(float4*)&Ks[r * PADW + c] = *(const float4*)(kbase + r * HDIM + c);
            *(float4*)&Vs[r * PADW + c] = *(const float4*)(vbase + r * HDIM + c);
        }
        __syncthreads();

        float s[4][4];
#pragma unroll
        for (int i = 0; i < 4; i++)
#pragma unroll
            for (int j = 0; j < 4; j++) s[i][j] = 0.f;

#pragma unroll 4
        for (int k = 0; k < 64; k += 4) {
            float qf[4][4], kf[4][4];
#pragma unroll
            for (int i = 0; i < 4; i++)
                *(float4*)qf[i] = *(const float4*)&Qs[(ty * 4 + i) * PADW + k];
#pragma unroll
            for (int i = 0; i < 4; i++)
                *(float4*)kf[i] = *(const float4*)&Ks[(tx * 4 + i) * PADW + k];
#pragma unroll
            for (int i = 0; i < 4; i++)
#pragma unroll
                for (int j = 0; j < 4; j++)
#pragma unroll
                    for (int kk = 0; kk < 4; kk++)
                        s[i][j] = fmaf(qf[i][kk], kf[j][kk], s[i][j]);
        }
#pragma unroll
        for (int i = 0; i < 4; i++)
            *(float4*)&Ss[(ty * 4 + i) * PADW + tx * 4] =
                make_float4(s[i][0], s[i][1], s[i][2], s[i][3]);
        __syncthreads();

        {
            int r = t >> 2, p = t & 3;
            float* srow = &Ss[r * PADW + p * 16];
            float mx = srow[0];
#pragma unroll
            for (int c = 1; c < 16; c++) mx = fmaxf(mx, srow[c]);
            mx = fmaxf(mx, __shfl_xor_sync(0xffffffffu, mx, 1));
            mx = fmaxf(mx, __shfl_xor_sync(0xffffffffu, mx, 2));
            float m_old = rowm[r];
            float m_new = fmaxf(m_old, mx);
            float sum = 0.f;
#pragma unroll
            for (int c = 0; c < 16; c++) {
                float e = __expf(srow[c] - m_new);
                srow[c] = e;
                sum += e;
            }
            sum += __shfl_xor_sync(0xffffffffu, sum, 1);
            sum += __shfl_xor_sync(0xffffffffu, sum, 2);
            if (p == 0) {
                float alpha = __expf(m_old - m_new);
                rowa[r] = alpha;
                rowm[r] = m_new;
                rowl[r] = rowl[r] * alpha + sum;
            }
        }
        __syncthreads();

        float alpha4[4];
#pragma unroll
        for (int i = 0; i < 4; i++) alpha4[i] = rowa[ty * 4 + i];
#pragma unroll
        for (int i = 0; i < 4; i++)
#pragma unroll
            for (int j = 0; j < 4; j++) o[i][j] *= alpha4[i];

#pragma unroll 4
        for (int k = 0; k < 64; k += 4) {
            float pf[4][4], vf[4][4];
#pragma unroll
            for (int i = 0; i < 4; i++)
                *(float4*)pf[i] = *(const float4*)&Ss[(ty * 4 + i) * PADW + k];
#pragma unroll
            for (int kk = 0; kk < 4; kk++)
                *(float4*)vf[kk] = *(const float4*)&Vs[(k + kk) * PADW + tx * 4];
#pragma unroll
            for (int i = 0; i < 4; i++)
#pragma unroll
                for (int j = 0; j < 4; j++) {
                    o[i][j] = fmaf(pf[i][0], vf[0][j], o[i][j]);
                    o[i][j] = fmaf(pf[i][1], vf[1][j], o[i][j]);
                    o[i][j] = fmaf(pf[i][2], vf[2][j], o[i][j]);
                    o[i][j] = fmaf(pf[i][3], vf[3][j], o[i][j]);
                }
        }
    }

    int b = bh >> 4, h = bh & 15;
#pragma unroll
    for (int i = 0; i < 4; i++) {
        float inv = 1.0f / rowl[ty * 4 + i];
        int tt = q0 + ty * 4 + i;
        float* dst = g_ctx + ((size_t)(b * SEQ + tt) * N_HEADS + h) * HDIM + tx * 4;
        *(float4*)dst = make_float4(o[i][0] * inv, o[i][1] * inv,
                                    o[i][2] * inv, o[i][3] * inv);
    }
}

// ---------------------------------------------------------------------------
extern "C" void kernel_launch(void* const* d_in, const int* in_sizes, int n_in,
                              void* d_out, int out_size)
{
    const float* query = (const float*)d_in[0];   // [4,2048,1024]
    const float* in_w  = (const float*)d_in[1];   // [3072,1024]
    const float* in_b  = (const float*)d_in[2];   // [3072]
    const float* out_w = (const float*)d_in[3];   // [1024,1024]
    const float* out_b = (const float*)d_in[4];   // [1024]
    float* out = (float*)d_out;                   // [4,2048,1024]

    cudaFuncSetAttribute(attn_kernel,
                         cudaFuncAttributeMaxDynamicSharedMemorySize,
                         ATTN_SMEM_BYTES);

    // 1) QKV projection + scatter to [B,H,T,D] (q scaled)
    gemm_mma<<<dim3(3 * E_DIM / 128, M_ROWS / 128), 256>>>(
        query, in_w, in_b, nullptr, E_DIM, 3 * E_DIM, 1);

    // 2) Flash attention -> g_ctx
    attn_kernel<<<dim3(SEQ / 64, BH_TOT), 256, ATTN_SMEM_BYTES>>>();

    // 3) Output projection -> d_out
    gemm_mma<<<dim3(E_DIM / 128, M_ROWS / 128), 256>>>(
        nullptr, out_w, out_b, out, E_DIM, E_DIM, 0);
}

// round 9
// speedup vs baseline: 3.7166x; 2.6415x over previous
#include <cuda_runtime.h>
#include <cstdint>

// Problem constants
#define E_DIM   1024
#define N_HEADS 16
#define HDIM    64
#define NB      4
#define SEQ     2048
#define BH_TOT  (NB * N_HEADS)   // 64
#define M_ROWS  (NB * SEQ)       // 8192
#define QKV_PAIRS (BH_TOT * SEQ * HDIM / 2)   // 4194304 bf16x2 pairs

// Scratch (device globals: no allocation allowed)
// q/k/v stored as bf16 hi/lo planes, packed as bf16x2 pairs along D.
__device__ uint32_t g_qh[QKV_PAIRS], g_ql[QKV_PAIRS];
__device__ uint32_t g_kh[QKV_PAIRS], g_kl[QKV_PAIRS];
__device__ uint32_t g_vh[QKV_PAIRS], g_vl[QKV_PAIRS];
__device__ float g_ctx[M_ROWS * E_DIM];      // [B,T,H*D] fp32

// ---- helpers ---------------------------------------------------------------
__device__ __forceinline__ uint32_t smem_u32(const void* p) {
    uint32_t a;
    asm("{ .reg .u64 t; cvta.to.shared.u64 t, %1; cvt.u32.u64 %0, t; }"
        : "=r"(a) : "l"(p));
    return a;
}
// pack two f32 -> bf16x2 (e0 in low 16 bits)
__device__ __forceinline__ uint32_t bf2(float e0, float e1) {
    uint32_t r;
    asm("cvt.rn.bf16x2.f32 %0, %1, %2;" : "=r"(r) : "f"(e1), "f"(e0));
    return r;
}
__device__ __forceinline__ float bf_lo_f32(uint32_t p) {
    return __uint_as_float(p << 16);
}
__device__ __forceinline__ float bf_hi_f32(uint32_t p) {
    return __uint_as_float(p & 0xffff0000u);
}

#define LDSM_X4(r0, r1, r2, r3, addr)                                        \
    asm volatile("ldmatrix.sync.aligned.m8n8.x4.shared.b16 "                 \
                 "{%0, %1, %2, %3}, [%4];"                                   \
                 : "=r"(r0), "=r"(r1), "=r"(r2), "=r"(r3) : "r"(addr))

#define LDSM_X4_T(r0, r1, r2, r3, addr)                                      \
    asm volatile("ldmatrix.sync.aligned.m8n8.x4.trans.shared.b16 "           \
                 "{%0, %1, %2, %3}, [%4];"                                   \
                 : "=r"(r0), "=r"(r1), "=r"(r2), "=r"(r3) : "r"(addr))

#define MMA_BF16(c, a, b)                                                    \
    asm volatile("mma.sync.aligned.m16n8k16.row.col.f32.bf16.bf16.f32 "      \
                 "{%0, %1, %2, %3}, {%4, %5, %6, %7}, {%8, %9}, "            \
                 "{%0, %1, %2, %3};"                                         \
                 : "+f"((c)[0]), "+f"((c)[1]), "+f"((c)[2]), "+f"((c)[3])    \
                 : "r"((a)[0]), "r"((a)[1]), "r"((a)[2]), "r"((a)[3]),       \
                   "r"((b)[0]), "r"((b)[1]))

// ===========================================================================
// bf16x3 tensor-core NT GEMM (proven in R6).
// mode 0: C[M,N].  mode 1: QKV scatter to bf16 hi/lo planes (q *= 0.125).
// ===========================================================================
#define SROW 40   // bf16 elems per smem row (32 data + 8 pad)

__global__ __launch_bounds__(256) void gemm_mma(
    const float* __restrict__ A, const float* __restrict__ W,
    const float* __restrict__ bias, float* __restrict__ C,
    int K, int N, int mode)
{
    __shared__ uint16_t As_hi[128 * SROW];
    __shared__ uint16_t As_lo[128 * SROW];
    __shared__ uint16_t Ws_hi[128 * SROW];
    __shared__ uint16_t Ws_lo[128 * SROW];

    const float* Ain = A ? A : g_ctx;

    int t    = threadIdx.x;
    int lane = t & 31;
    int wid  = t >> 5;
    int wm   = wid >> 2;          // 0..1
    int wn   = wid & 3;           // 0..3
    int gid  = lane >> 2;
    int tig  = lane & 3;

    int rbase = blockIdx.y * 128;
    int cbase = blockIdx.x * 128;

    uint32_t lm_off = (uint32_t)((lane & 15) * SROW + ((lane >> 4) << 3)) * 2;
    uint32_t aHiB = smem_u32(As_hi) + (uint32_t)(wm * 64 * SROW * 2) + lm_off;
    uint32_t aLoB = smem_u32(As_lo) + (uint32_t)(wm * 64 * SROW * 2) + lm_off;
    uint32_t bHiB = smem_u32(Ws_hi) + (uint32_t)(wn * 32 * SROW * 2) + lm_off;
    uint32_t bLoB = smem_u32(Ws_lo) + (uint32_t)(wn * 32 * SROW * 2) + lm_off;

    float acc[4][4][4];
#pragma unroll
    for (int i = 0; i < 4; i++)
#pragma unroll
        for (int j = 0; j < 4; j++)
#pragma unroll
            for (int r = 0; r < 4; r++) acc[i][j][r] = 0.f;

    const int nch = K / 32;
    for (int ch = 0; ch < nch; ch++) {
        int k0 = ch * 32;
        __syncthreads();
#pragma unroll
        for (int q = 0; q < 4; q++) {
            int idx = t + 256 * q;
            int row = idx >> 3;
            int c4  = (idx & 7) << 2;
            uint32_t so = (uint32_t)(row * SROW + c4);

            float4 a = *(const float4*)(Ain + (size_t)(rbase + row) * K + k0 + c4);
            uint32_t h01 = bf2(a.x, a.y), h23 = bf2(a.z, a.w);
            uint32_t l01 = bf2(a.x - bf_lo_f32(h01), a.y - bf_hi_f32(h01));
            uint32_t l23 = bf2(a.z - bf_lo_f32(h23), a.w - bf_hi_f32(h23));
            *(uint2*)&As_hi[so] = make_uint2(h01, h23);
            *(uint2*)&As_lo[so] = make_uint2(l01, l23);

            float4 b = *(const float4*)(W + (size_t)(cbase + row) * K + k0 + c4);
            uint32_t wh01 = bf2(b.x, b.y), wh23 = bf2(b.z, b.w);
            uint32_t wl01 = bf2(b.x - bf_lo_f32(wh01), b.y - bf_hi_f32(wh01));
            uint32_t wl23 = bf2(b.z - bf_lo_f32(wh23), b.w - bf_hi_f32(wh23));
            *(uint2*)&Ws_hi[so] = make_uint2(wh01, wh23);
            *(uint2*)&Ws_lo[so] = make_uint2(wl01, wl23);
        }
        __syncthreads();

#pragma unroll
        for (int kk = 0; kk < 2; kk++) {
            uint32_t kb = (uint32_t)(kk * 16 * 2);
            uint32_t Ah[4][4], Al[4][4], Bh[4][2], Bl[4][2];
#pragma unroll
            for (int mt = 0; mt < 4; mt++) {
                uint32_t off = kb + (uint32_t)(mt * 16 * SROW * 2);
                LDSM_X4(Ah[mt][0], Ah[mt][1], Ah[mt][2], Ah[mt][3], aHiB + off);
                LDSM_X4(Al[mt][0], Al[mt][1], Al[mt][2], Al[mt][3], aLoB + off);
            }
#pragma unroll
            for (int nt2 = 0; nt2 < 2; nt2++) {
                uint32_t off = kb + (uint32_t)(nt2 * 16 * SROW * 2);
                uint32_t r0, r1, r2, r3;
                LDSM_X4(r0, r1, r2, r3, bHiB + off);
                Bh[nt2 * 2][0] = r0; Bh[nt2 * 2 + 1][0] = r1;
                Bh[nt2 * 2][1] = r2; Bh[nt2 * 2 + 1][1] = r3;
                LDSM_X4(r0, r1, r2, r3, bLoB + off);
                Bl[nt2 * 2][0] = r0; Bl[nt2 * 2 + 1][0] = r1;
                Bl[nt2 * 2][1] = r2; Bl[nt2 * 2 + 1][1] = r3;
            }
#pragma unroll
            for (int mt = 0; mt < 4; mt++)
#pragma unroll
                for (int nt = 0; nt < 4; nt++) {
                    MMA_BF16(acc[mt][nt], Ah[mt], Bh[nt]);
                    MMA_BF16(acc[mt][nt], Ah[mt], Bl[nt]);
                    MMA_BF16(acc[mt][nt], Al[mt], Bh[nt]);
                }
        }
    }

#pragma unroll
    for (int mt = 0; mt < 4; mt++) {
#pragma unroll
        for (int nt = 0; nt < 4; nt++) {
            int n = cbase + wn * 32 + nt * 8 + 2 * tig;
            float bz0 = bias[n], bz1 = bias[n + 1];
#pragma unroll
            for (int half = 0; half < 2; half++) {
                int m = rbase + wm * 64 + mt * 16 + gid + half * 8;
                float v0 = acc[mt][nt][half * 2]     + bz0;
                float v1 = acc[mt][nt][half * 2 + 1] + bz1;
                if (mode == 0) {
                    *(float2*)&C[(size_t)m * N + n] = make_float2(v0, v1);
                } else {
                    int part = n >> 10;
                    int rr   = n & 1023;
                    int h    = rr >> 6;
                    int d    = rr & 63;
                    int b    = m >> 11;
                    int tt   = m & 2047;
                    int pidx = (((b * N_HEADS + h) * SEQ + tt) * HDIM + d) >> 1;
                    if (part == 0) { v0 *= 0.125f; v1 *= 0.125f; }
                    uint32_t hi = bf2(v0, v1);
                    uint32_t lo = bf2(v0 - bf_lo_f32(hi), v1 - bf_hi_f32(hi));
                    if (part == 0)      { g_qh[pidx] = hi; g_ql[pidx] = lo; }
                    else if (part == 1) { g_kh[pidx] = hi; g_kl[pidx] = lo; }
                    else                { g_vh[pidx] = hi; g_vl[pidx] = lo; }
                }
            }
        }
    }
}

// ===========================================================================
// Tensor-core flash attention (bf16x3). Block = 128 q-rows x (b,h).
// 8 warps, each owns 16 q-rows; softmax is register/quad-shuffle local.
// K/V tiles of 64 rows staged as hi/lo bf16 planes.
// ===========================================================================
#define QROW 72   // bf16 per smem row (64 data + 8 pad); 144B, 16B-aligned
#define ATTN_SMEM ((2 * 128 + 4 * 64) * QROW * 2)   // 73728 bytes

__global__ __launch_bounds__(256) void attn_mma()
{
    extern __shared__ char smraw[];
    uint16_t* Qh = (uint16_t*)smraw;            // [128][QROW]
    uint16_t* Ql = Qh + 128 * QROW;
    uint16_t* Kh = Ql + 128 * QROW;             // [64][QROW]
    uint16_t* Kl = Kh + 64 * QROW;
    uint16_t* Vh = Kl + 64 * QROW;
    uint16_t* Vl = Vh + 64 * QROW;

    int t    = threadIdx.x;
    int lane = t & 31;
    int w    = t >> 5;
    int gid  = lane >> 2;
    int tig  = lane & 3;
    int bh   = blockIdx.y;
    int q0   = blockIdx.x * 128;

    // ---- stage Q (hi/lo pairs) into smem ----
    const uint4* gqh = (const uint4*)(g_qh + ((size_t)bh * SEQ + q0) * 32);
    const uint4* gql = (const uint4*)(g_ql + ((size_t)bh * SEQ + q0) * 32);
#pragma unroll
    for (int i = 0; i < 4; i++) {
        int idx = t + 256 * i;         // 0..1023 uint4 slots (128 rows x 8)
        int r   = idx >> 3;
        int c4  = (idx & 7) << 2;      // pair offset (x4)
        *(uint4*)&Qh[r * QROW + 2 * c4] = gqh[r * 8 + (idx & 7)];
        *(uint4*)&Ql[r * QROW + 2 * c4] = gql[r * 8 + (idx & 7)];
    }
    __syncthreads();

    // ---- load Q fragments to registers (constant over k-loop) ----
    uint32_t lmA = (uint32_t)((w * 16 + (lane & 15)) * QROW + ((lane >> 4) << 3)) * 2;
    uint32_t qhA = smem_u32(Qh) + lmA;
    uint32_t qlA = smem_u32(Ql) + lmA;
    uint32_t Qfh[4][4], Qfl[4][4];
#pragma unroll
    for (int kt = 0; kt < 4; kt++) {
        LDSM_X4(Qfh[kt][0], Qfh[kt][1], Qfh[kt][2], Qfh[kt][3], qhA + kt * 32);
        LDSM_X4(Qfl[kt][0], Qfl[kt][1], Qfl[kt][2], Qfl[kt][3], qlA + kt * 32);
    }

    uint32_t lmB = (uint32_t)((lane & 15) * QROW + ((lane >> 4) << 3)) * 2;
    uint32_t khB = smem_u32(Kh) + lmB;
    uint32_t klB = smem_u32(Kl) + lmB;
    uint32_t vhB = smem_u32(Vh) + lmB;
    uint32_t vlB = smem_u32(Vl) + lmB;

    float O[8][4];
#pragma unroll
    for (int nt = 0; nt < 8; nt++)
#pragma unroll
        for (int r = 0; r < 4; r++) O[nt][r] = 0.f;
    float m0 = -1e30f, m1 = -1e30f, l0 = 0.f, l1 = 0.f;

    const uint4* gkh = (const uint4*)(g_kh + (size_t)bh * SEQ * 32);
    const uint4* gkl = (const uint4*)(g_kl + (size_t)bh * SEQ * 32);
    const uint4* gvh = (const uint4*)(g_vh + (size_t)bh * SEQ * 32);
    const uint4* gvl = (const uint4*)(g_vl + (size_t)bh * SEQ * 32);

    for (int jt = 0; jt < SEQ / 64; jt++) {
        __syncthreads();
        // stage K/V tile (64 rows, 8 uint4 per row per plane)
        int rowoff = jt * 64 * 8;
#pragma unroll
        for (int i = 0; i < 2; i++) {
            int idx = t + 256 * i;     // 0..511
            int r   = idx >> 3;
            int c   = idx & 7;
            uint32_t so = (uint32_t)(r * QROW + 8 * c);
            *(uint4*)&Kh[so] = gkh[rowoff + r * 8 + c];
            *(uint4*)&Kl[so] = gkl[rowoff + r * 8 + c];
            *(uint4*)&Vh[so] = gvh[rowoff + r * 8 + c];
            *(uint4*)&Vl[so] = gvl[rowoff + r * 8 + c];
        }
        __syncthreads();

        // ---- S = Q K^T (bf16x3) ----
        float s[8][4];
#pragma unroll
        for (int nt = 0; nt < 8; nt++)
#pragma unroll
            for (int r = 0; r < 4; r++) s[nt][r] = 0.f;

#pragma unroll
        for (int kt = 0; kt < 4; kt++) {
            uint32_t KfH[8][2], KfL[8][2];
#pragma unroll
            for (int p = 0; p < 4; p++) {   // j0 = p*16 -> ntiles 2p, 2p+1
                uint32_t off = (uint32_t)(p * 16 * QROW * 2) + kt * 32;
                uint32_t r0, r1, r2, r3;
                LDSM_X4(r0, r1, r2, r3, khB + off);
                KfH[2 * p][0] = r0; KfH[2 * p + 1][0] = r1;
                KfH[2 * p][1] = r2; KfH[2 * p + 1][1] = r3;
                LDSM_X4(r0, r1, r2, r3, klB + off);
                KfL[2 * p][0] = r0; KfL[2 * p + 1][0] = r1;
                KfL[2 * p][1] = r2; KfL[2 * p + 1][1] = r3;
            }
#pragma unroll
            for (int nt = 0; nt < 8; nt++) {
                MMA_BF16(s[nt], Qfh[kt], KfH[nt]);
                MMA_BF16(s[nt], Qfh[kt], KfL[nt]);
                MMA_BF16(s[nt], Qfl[kt], KfH[nt]);
            }
        }

        // ---- online softmax (register + quad shuffle) ----
        float mx0 = s[0][0], mx1 = s[0][2];
#pragma unroll
        for (int nt = 0; nt < 8; nt++) {
            mx0 = fmaxf(mx0, fmaxf(s[nt][0], s[nt][1]));
            mx1 = fmaxf(mx1, fmaxf(s[nt][2], s[nt][3]));
        }
        mx0 = fmaxf(mx0, __shfl_xor_sync(0xffffffffu, mx0, 1));
        mx0 = fmaxf(mx0, __shfl_xor_sync(0xffffffffu, mx0, 2));
        mx1 = fmaxf(mx1, __shfl_xor_sync(0xffffffffu, mx1, 1));
        mx1 = fmaxf(mx1, __shfl_xor_sync(0xffffffffu, mx1, 2));

        float mn0 = fmaxf(m0, mx0), mn1 = fmaxf(m1, mx1);
        float a0 = __expf(m0 - mn0), a1 = __expf(m1 - mn1);
        m0 = mn0; m1 = mn1;

        float sum0 = 0.f, sum1 = 0.f;
#pragma unroll
        for (int nt = 0; nt < 8; nt++) {
            s[nt][0] = __expf(s[nt][0] - mn0);
            s[nt][1] = __expf(s[nt][1] - mn0);
            s[nt][2] = __expf(s[nt][2] - mn1);
            s[nt][3] = __expf(s[nt][3] - mn1);
            sum0 += s[nt][0] + s[nt][1];
            sum1 += s[nt][2] + s[nt][3];
        }
        sum0 += __shfl_xor_sync(0xffffffffu, sum0, 1);
        sum0 += __shfl_xor_sync(0xffffffffu, sum0, 2);
        sum1 += __shfl_xor_sync(0xffffffffu, sum1, 1);
        sum1 += __shfl_xor_sync(0xffffffffu, sum1, 2);
        l0 = l0 * a0 + sum0;
        l1 = l1 * a1 + sum1;

#pragma unroll
        for (int nt = 0; nt < 8; nt++) {
            O[nt][0] *= a0; O[nt][1] *= a0;
            O[nt][2] *= a1; O[nt][3] *= a1;
        }

        // ---- P fragments (hi/lo) from S accumulators ----
        uint32_t Pah[4][4], Pal[4][4];
#pragma unroll
        for (int kt = 0; kt < 4; kt++) {
            int e = 2 * kt, o = 2 * kt + 1;
            uint32_t h;
            h = bf2(s[e][0], s[e][1]);
            Pah[kt][0] = h;
            Pal[kt][0] = bf2(s[e][0] - bf_lo_f32(h), s[e][1] - bf_hi_f32(h));
            h = bf2(s[e][2], s[e][3]);
            Pah[kt][1] = h;
            Pal[kt][1] = bf2(s[e][2] - bf_lo_f32(h), s[e][3] - bf_hi_f32(h));
            h = bf2(s[o][0], s[o][1]);
            Pah[kt][2] = h;
            Pal[kt][2] = bf2(s[o][0] - bf_lo_f32(h), s[o][1] - bf_hi_f32(h));
            h = bf2(s[o][2], s[o][3]);
            Pah[kt][3] = h;
            Pal[kt][3] = bf2(s[o][2] - bf_lo_f32(h), s[o][3] - bf_hi_f32(h));
        }

        // ---- O += P V (bf16x3, V via ldmatrix.trans) ----
#pragma unroll
        for (int kt = 0; kt < 4; kt++) {
            uint32_t VfH[8][2], VfL[8][2];
#pragma unroll
            for (int p = 0; p < 4; p++) {   // d0 = p*16 -> ntiles 2p, 2p+1
                uint32_t off = (uint32_t)(kt * 16 * QROW * 2) + (uint32_t)(p * 16 * 2);
                uint32_t r0, r1, r2, r3;
                LDSM_X4_T(r0, r1, r2, r3, vhB + off);
                VfH[2 * p][0] = r0; VfH[2 * p][1] = r1;
                VfH[2 * p + 1][0] = r2; VfH[2 * p + 1][1] = r3;
                LDSM_X4_T(r0, r1, r2, r3, vlB + off);
                VfL[2 * p][0] = r0; VfL[2 * p][1] = r1;
                VfL[2 * p + 1][0] = r2; VfL[2 * p + 1][1] = r3;
            }
#pragma unroll
            for (int nt = 0; nt < 8; nt++) {
                MMA_BF16(O[nt], Pah[kt], VfH[nt]);
                MMA_BF16(O[nt], Pah[kt], VfL[nt]);
                MMA_BF16(O[nt], Pal[kt], VfH[nt]);
            }
        }
    }

    // ---- epilogue: normalize, write g_ctx [B,T,H,D] fp32 ----
    float inv0 = 1.0f / l0, inv1 = 1.0f / l1;
    int b = bh >> 4, h = bh & 15;
    int r0g = q0 + w * 16 + gid;
    int r1g = r0g + 8;
#pragma unroll
    for (int nt = 0; nt < 8; nt++) {
        int d = nt * 8 + 2 * tig;
        float* p0 = g_ctx + ((size_t)(b * SEQ + r0g) * N_HEADS + h) * HDIM + d;
        float* p1 = g_ctx + ((size_t)(b * SEQ + r1g) * N_HEADS + h) * HDIM + d;
        *(float2*)p0 = make_float2(O[nt][0] * inv0, O[nt][1] * inv0);
        *(float2*)p1 = make_float2(O[nt][2] * inv1, O[nt][3] * inv1);
    }
}

// ---------------------------------------------------------------------------
extern "C" void kernel_launch(void* const* d_in, const int* in_sizes, int n_in,
                              void* d_out, int out_size)
{
    const float* query = (const float*)d_in[0];   // [4,2048,1024]
    const float* in_w  = (const float*)d_in[1];   // [3072,1024]
    const float* in_b  = (const float*)d_in[2];   // [3072]
    const float* out_w = (const float*)d_in[3];   // [1024,1024]
    const float* out_b = (const float*)d_in[4];   // [1024]
    float* out = (float*)d_out;                   // [4,2048,1024]

    cudaFuncSetAttribute(attn_mma,
                         cudaFuncAttributeMaxDynamicSharedMemorySize, ATTN_SMEM);

    // 1) QKV projection + scatter to bf16 hi/lo planes (q scaled)
    gemm_mma<<<dim3(3 * E_DIM / 128, M_ROWS / 128), 256>>>(
        query, in_w, in_b, nullptr, E_DIM, 3 * E_DIM, 1);

    // 2) Tensor-core flash attention -> g_ctx
    attn_mma<<<dim3(SEQ / 128, BH_TOT), 256, ATTN_SMEM>>>();

    // 3) Output projection -> d_out
    gemm_mma<<<dim3(E_DIM / 128, M_ROWS / 128), 256>>>(
        nullptr, out_w, out_b, out, E_DIM, E_DIM, 0);
}

// round 10
// speedup vs baseline: 3.9463x; 1.0618x over previous
#include <cuda_runtime.h>
#include <cstdint>

// Problem constants
#define E_DIM   1024
#define N_HEADS 16
#define HDIM    64
#define NB      4
#define SEQ     2048
#define BH_TOT  (NB * N_HEADS)   // 64
#define M_ROWS  (NB * SEQ)       // 8192
#define QKV_PAIRS (BH_TOT * SEQ * HDIM / 2)   // 4194304

// Scratch (device globals: no allocation allowed). All bf16x2-pair planes.
__device__ uint32_t g_ah[M_ROWS * E_DIM / 2], g_al[M_ROWS * E_DIM / 2];   // query
__device__ uint32_t g_wh[3 * E_DIM * E_DIM / 2], g_wl[3 * E_DIM * E_DIM / 2];
__device__ uint32_t g_oh[E_DIM * E_DIM / 2], g_ol[E_DIM * E_DIM / 2];
__device__ uint32_t g_ch[M_ROWS * E_DIM / 2], g_cl[M_ROWS * E_DIM / 2];   // ctx
__device__ uint32_t g_qh[QKV_PAIRS], g_ql[QKV_PAIRS];
__device__ uint32_t g_kh[QKV_PAIRS], g_kl[QKV_PAIRS];
__device__ uint32_t g_vh[QKV_PAIRS], g_vl[QKV_PAIRS];

// ---- helpers ---------------------------------------------------------------
__device__ __forceinline__ uint32_t smem_u32(const void* p) {
    uint32_t a;
    asm("{ .reg .u64 t; cvta.to.shared.u64 t, %1; cvt.u32.u64 %0, t; }"
        : "=r"(a) : "l"(p));
    return a;
}
__device__ __forceinline__ uint32_t bf2(float e0, float e1) {
    uint32_t r;
    asm("cvt.rn.bf16x2.f32 %0, %1, %2;" : "=r"(r) : "f"(e1), "f"(e0));
    return r;
}
__device__ __forceinline__ float bf_lo_f32(uint32_t p) {
    return __uint_as_float(p << 16);
}
__device__ __forceinline__ float bf_hi_f32(uint32_t p) {
    return __uint_as_float(p & 0xffff0000u);
}

__device__ __forceinline__ void cp16(uint32_t dst, const void* src) {
    asm volatile("cp.async.cg.shared.global [%0], [%1], 16;"
                 :: "r"(dst), "l"(src) : "memory");
}
#define CP_COMMIT asm volatile("cp.async.commit_group;" ::: "memory")
#define CP_WAIT0  asm volatile("cp.async.wait_group 0;" ::: "memory")
#define CP_WAIT1  asm volatile("cp.async.wait_group 1;" ::: "memory")

#define LDSM_X4(r0, r1, r2, r3, addr)                                        \
    asm volatile("ldmatrix.sync.aligned.m8n8.x4.shared.b16 "                 \
                 "{%0, %1, %2, %3}, [%4];"                                   \
                 : "=r"(r0), "=r"(r1), "=r"(r2), "=r"(r3) : "r"(addr))

#define LDSM_X4_T(r0, r1, r2, r3, addr)                                      \
    asm volatile("ldmatrix.sync.aligned.m8n8.x4.trans.shared.b16 "           \
                 "{%0, %1, %2, %3}, [%4];"                                   \
                 : "=r"(r0), "=r"(r1), "=r"(r2), "=r"(r3) : "r"(addr))

#define MMA_BF16(c, a, b)                                                    \
    asm volatile("mma.sync.aligned.m16n8k16.row.col.f32.bf16.bf16.f32 "      \
                 "{%0, %1, %2, %3}, {%4, %5, %6, %7}, {%8, %9}, "            \
                 "{%0, %1, %2, %3};"                                         \
                 : "+f"((c)[0]), "+f"((c)[1]), "+f"((c)[2]), "+f"((c)[3])    \
                 : "r"((a)[0]), "r"((a)[1]), "r"((a)[2]), "r"((a)[3]),       \
                   "r"((b)[0]), "r"((b)[1]))

// ===========================================================================
// One-pass fp32 -> bf16 hi/lo plane split.  which: 0=query 1=in_w 2=out_w
// ===========================================================================
__global__ __launch_bounds__(256) void conv_split(const float4* __restrict__ src,
                                                  int which, int n4)
{
    int i = blockIdx.x * 256 + threadIdx.x;
    if (i >= n4) return;
    uint2* hi = (uint2*)(which == 0 ? g_ah : (which == 1 ? g_wh : g_oh));
    uint2* lo = (uint2*)(which == 0 ? g_al : (which == 1 ? g_wl : g_ol));
    float4 a = src[i];
    uint32_t h01 = bf2(a.x, a.y), h23 = bf2(a.z, a.w);
    uint32_t l01 = bf2(a.x - bf_lo_f32(h01), a.y - bf_hi_f32(h01));
    uint32_t l23 = bf2(a.z - bf_lo_f32(h23), a.w - bf_hi_f32(h23));
    hi[i] = make_uint2(h01, h23);
    lo[i] = make_uint2(l01, l23);
}

// ===========================================================================
// bf16x3 tensor-core NT GEMM v2: pre-split operands + cp.async double buffer.
// which 0: A=g_ah/al, W=g_wh/wl, scatter-QKV epilogue (q *= 0.125)
// which 1: A=g_ch/cl, W=g_oh/ol, C-store epilogue
// ===========================================================================
#define SROW 40                        // bf16 per smem row (32 data + 8 pad)
#define GPLANE (128 * SROW * 2)        // 10240 B
#define GSTAGE (4 * GPLANE)            // 40960 B
#define GEMM_SMEM2 (2 * GSTAGE)        // 81920 B

__device__ __forceinline__ void stage_gemm(
    uint32_t stb, int t, int ch, int kd8,
    const uint4* Ah, const uint4* Al, const uint4* Wh, const uint4* Wl,
    int rbase, int cbase)
{
    const uint4* b0 = Ah + (size_t)rbase * kd8 + ch * 4;
    const uint4* b1 = Al + (size_t)rbase * kd8 + ch * 4;
    const uint4* b2 = Wh + (size_t)cbase * kd8 + ch * 4;
    const uint4* b3 = Wl + (size_t)cbase * kd8 + ch * 4;
#pragma unroll
    for (int half = 0; half < 2; half++) {
        int g = t + 256 * half;        // 0..511
        int row = g >> 2, c = g & 3;
        uint32_t d = stb + (uint32_t)(row * SROW * 2 + c * 16);
        size_t si = (size_t)row * kd8 + c;
        cp16(d + 0 * GPLANE, b0 + si);
        cp16(d + 1 * GPLANE, b1 + si);
        cp16(d + 2 * GPLANE, b2 + si);
        cp16(d + 3 * GPLANE, b3 + si);
    }
}

__global__ __launch_bounds__(256) void gemm_v2(
    const float* __restrict__ bias, float* __restrict__ C,
    int K, int N, int which)
{
    extern __shared__ char smraw[];
    uint32_t sbase = smem_u32(smraw);

    const uint4* Ah = (const uint4*)(which == 0 ? g_ah : g_ch);
    const uint4* Al = (const uint4*)(which == 0 ? g_al : g_cl);
    const uint4* Wh = (const uint4*)(which == 0 ? g_wh : g_oh);
    const uint4* Wl = (const uint4*)(which == 0 ? g_wl : g_ol);

    int t    = threadIdx.x;
    int lane = t & 31;
    int wid  = t >> 5;
    int wm   = wid >> 2;
    int wn   = wid & 3;
    int gid  = lane >> 2;
    int tig  = lane & 3;

    int rbase = blockIdx.y * 128;
    int cbase = blockIdx.x * 128;
    int kd8   = K >> 3;

    uint32_t lm_off = (uint32_t)((lane & 15) * SROW + ((lane >> 4) << 3)) * 2;

    float acc[4][4][4];
#pragma unroll
    for (int i = 0; i < 4; i++)
#pragma unroll
        for (int j = 0; j < 4; j++)
#pragma unroll
            for (int r = 0; r < 4; r++) acc[i][j][r] = 0.f;

    const int nch = K / 32;
    stage_gemm(sbase, t, 0, kd8, Ah, Al, Wh, Wl, rbase, cbase);
    CP_COMMIT;

    for (int ch = 0; ch < nch; ch++) {
        if (ch + 1 < nch) {
            stage_gemm(sbase + ((ch + 1) & 1) * GSTAGE, t, ch + 1, kd8,
                       Ah, Al, Wh, Wl, rbase, cbase);
            CP_COMMIT;
            CP_WAIT1;
        } else {
            CP_WAIT0;
        }
        __syncthreads();

        uint32_t stb  = sbase + (ch & 1) * GSTAGE;
        uint32_t aHiB = stb + (uint32_t)(wm * 64 * SROW * 2) + lm_off;
        uint32_t aLoB = aHiB + GPLANE;
        uint32_t bHiB = stb + 2 * GPLANE + (uint32_t)(wn * 32 * SROW * 2) + lm_off;
        uint32_t bLoB = bHiB + GPLANE;

#pragma unroll
        for (int kk = 0; kk < 2; kk++) {
            uint32_t kb = (uint32_t)(kk * 16 * 2);
            uint32_t Ahf[4][4], Alf[4][4], Bh[4][2], Bl[4][2];
#pragma unroll
            for (int mt = 0; mt < 4; mt++) {
                uint32_t off = kb + (uint32_t)(mt * 16 * SROW * 2);
                LDSM_X4(Ahf[mt][0], Ahf[mt][1], Ahf[mt][2], Ahf[mt][3], aHiB + off);
                LDSM_X4(Alf[mt][0], Alf[mt][1], Alf[mt][2], Alf[mt][3], aLoB + off);
            }
#pragma unroll
            for (int nt2 = 0; nt2 < 2; nt2++) {
                uint32_t off = kb + (uint32_t)(nt2 * 16 * SROW * 2);
                uint32_t r0, r1, r2, r3;
                LDSM_X4(r0, r1, r2, r3, bHiB + off);
                Bh[nt2 * 2][0] = r0; Bh[nt2 * 2 + 1][0] = r1;
                Bh[nt2 * 2][1] = r2; Bh[nt2 * 2 + 1][1] = r3;
                LDSM_X4(r0, r1, r2, r3, bLoB + off);
                Bl[nt2 * 2][0] = r0; Bl[nt2 * 2 + 1][0] = r1;
                Bl[nt2 * 2][1] = r2; Bl[nt2 * 2 + 1][1] = r3;
            }
#pragma unroll
            for (int mt = 0; mt < 4; mt++)
#pragma unroll
                for (int nt = 0; nt < 4; nt++) {
                    MMA_BF16(acc[mt][nt], Ahf[mt], Bh[nt]);
                    MMA_BF16(acc[mt][nt], Ahf[mt], Bl[nt]);
                    MMA_BF16(acc[mt][nt], Alf[mt], Bh[nt]);
                }
        }
        __syncthreads();
    }

#pragma unroll
    for (int mt = 0; mt < 4; mt++) {
#pragma unroll
        for (int nt = 0; nt < 4; nt++) {
            int n = cbase + wn * 32 + nt * 8 + 2 * tig;
            float bz0 = bias[n], bz1 = bias[n + 1];
#pragma unroll
            for (int half = 0; half < 2; half++) {
                int m = rbase + wm * 64 + mt * 16 + gid + half * 8;
                float v0 = acc[mt][nt][half * 2]     + bz0;
                float v1 = acc[mt][nt][half * 2 + 1] + bz1;
                if (which == 1) {
                    *(float2*)&C[(size_t)m * N + n] = make_float2(v0, v1);
                } else {
                    int part = n >> 10;
                    int rr   = n & 1023;
                    int h    = rr >> 6;
                    int d    = rr & 63;
                    int b    = m >> 11;
                    int tt   = m & 2047;
                    int pidx = (((b * N_HEADS + h) * SEQ + tt) * HDIM + d) >> 1;
                    if (part == 0) { v0 *= 0.125f; v1 *= 0.125f; }
                    uint32_t hi = bf2(v0, v1);
                    uint32_t lo = bf2(v0 - bf_lo_f32(hi), v1 - bf_hi_f32(hi));
                    if (part == 0)      { g_qh[pidx] = hi; g_ql[pidx] = lo; }
                    else if (part == 1) { g_kh[pidx] = hi; g_kl[pidx] = lo; }
                    else                { g_vh[pidx] = hi; g_vl[pidx] = lo; }
                }
            }
        }
    }
}

// ===========================================================================
// Tensor-core flash attention (bf16x3) + cp.async double-buffered K/V.
// Block = 128 q-rows x (b,h); 8 warps x 16 rows; register softmax.
// Epilogue writes ctx directly as bf16 hi/lo planes.
// ===========================================================================
#define QROW 72                         // 64 data + 8 pad bf16; 144 B rows
#define KVPLANE (64 * QROW * 2)         // 9216 B
#define KVSTAGE (4 * KVPLANE)           // 36864 B
#define ATTN_SMEM2 (2 * 128 * QROW * 2 + 2 * KVSTAGE)   // 110592 B

__device__ __forceinline__ void stage_kv(uint32_t stb, int t, int rowoff,
    const uint4* kh, const uint4* kl, const uint4* vh, const uint4* vl)
{
#pragma unroll
    for (int half = 0; half < 2; half++) {
        int g = t + 256 * half;         // 0..511
        int row = g >> 3, c = g & 7;
        uint32_t d = stb + (uint32_t)(row * QROW * 2 + c * 16);
        int si = rowoff + row * 8 + c;
        cp16(d + 0 * KVPLANE, kh + si);
        cp16(d + 1 * KVPLANE, kl + si);
        cp16(d + 2 * KVPLANE, vh + si);
        cp16(d + 3 * KVPLANE, vl + si);
    }
}

__global__ __launch_bounds__(256) void attn_v2()
{
    extern __shared__ char smraw[];
    uint16_t* Qh = (uint16_t*)smraw;                 // [128][QROW]
    uint16_t* Ql = Qh + 128 * QROW;
    uint32_t kvbase = smem_u32(smraw) + 2 * 128 * QROW * 2;

    int t    = threadIdx.x;
    int lane = t & 31;
    int w    = t >> 5;
    int gid  = lane >> 2;
    int tig  = lane & 3;
    int bh   = blockIdx.y;
    int q0   = blockIdx.x * 128;

    const uint4* gkh = (const uint4*)(g_kh + (size_t)bh * SEQ * 32);
    const uint4* gkl = (const uint4*)(g_kl + (size_t)bh * SEQ * 32);
    const uint4* gvh = (const uint4*)(g_vh + (size_t)bh * SEQ * 32);
    const uint4* gvl = (const uint4*)(g_vl + (size_t)bh * SEQ * 32);

    // prefetch K/V tile 0 while staging Q
    stage_kv(kvbase, t, 0, gkh, gkl, gvh, gvl);
    CP_COMMIT;

    const uint4* gqh = (const uint4*)(g_qh + ((size_t)bh * SEQ + q0) * 32);
    const uint4* gql = (const uint4*)(g_ql + ((size_t)bh * SEQ + q0) * 32);
#pragma unroll
    for (int i = 0; i < 4; i++) {
        int idx = t + 256 * i;
        int r   = idx >> 3;
        int c4  = (idx & 7) << 2;
        *(uint4*)&Qh[r * QROW + 2 * c4] = gqh[r * 8 + (idx & 7)];
        *(uint4*)&Ql[r * QROW + 2 * c4] = gql[r * 8 + (idx & 7)];
    }
    __syncthreads();

    uint32_t lmA = (uint32_t)((w * 16 + (lane & 15)) * QROW + ((lane >> 4) << 3)) * 2;
    uint32_t qhA = smem_u32(Qh) + lmA;
    uint32_t qlA = smem_u32(Ql) + lmA;
    uint32_t Qfh[4][4], Qfl[4][4];
#pragma unroll
    for (int kt = 0; kt < 4; kt++) {
        LDSM_X4(Qfh[kt][0], Qfh[kt][1], Qfh[kt][2], Qfh[kt][3], qhA + kt * 32);
        LDSM_X4(Qfl[kt][0], Qfl[kt][1], Qfl[kt][2], Qfl[kt][3], qlA + kt * 32);
    }

    uint32_t lmB = (uint32_t)((lane & 15) * QROW + ((lane >> 4) << 3)) * 2;

    float O[8][4];
#pragma unroll
    for (int nt = 0; nt < 8; nt++)
#pragma unroll
        for (int r = 0; r < 4; r++) O[nt][r] = 0.f;
    float m0 = -1e30f, m1 = -1e30f, l0 = 0.f, l1 = 0.f;

    const int ntiles = SEQ / 64;
    for (int jt = 0; jt < ntiles; jt++) {
        if (jt + 1 < ntiles) {
            stage_kv(kvbase + ((jt + 1) & 1) * KVSTAGE, t, (jt + 1) * 64 * 8,
                     gkh, gkl, gvh, gvl);
            CP_COMMIT;
            CP_WAIT1;
        } else {
            CP_WAIT0;
        }
        __syncthreads();

        uint32_t kvb = kvbase + (jt & 1) * KVSTAGE;
        uint32_t khB = kvb + lmB;
        uint32_t klB = khB + KVPLANE;
        uint32_t vhB = khB + 2 * KVPLANE;
        uint32_t vlB = khB + 3 * KVPLANE;

        // ---- S = Q K^T (bf16x3) ----
        float s[8][4];
#pragma unroll
        for (int nt = 0; nt < 8; nt++)
#pragma unroll
            for (int r = 0; r < 4; r++) s[nt][r] = 0.f;

#pragma unroll
        for (int kt = 0; kt < 4; kt++) {
            uint32_t KfH[8][2], KfL[8][2];
#pragma unroll
            for (int p = 0; p < 4; p++) {
                uint32_t off = (uint32_t)(p * 16 * QROW * 2) + kt * 32;
                uint32_t r0, r1, r2, r3;
                LDSM_X4(r0, r1, r2, r3, khB + off);
                KfH[2 * p][0] = r0; KfH[2 * p + 1][0] = r1;
                KfH[2 * p][1] = r2; KfH[2 * p + 1][1] = r3;
                LDSM_X4(r0, r1, r2, r3, klB + off);
                KfL[2 * p][0] = r0; KfL[2 * p + 1][0] = r1;
                KfL[2 * p][1] = r2; KfL[2 * p + 1][1] = r3;
            }
#pragma unroll
            for (int nt = 0; nt < 8; nt++) {
                MMA_BF16(s[nt], Qfh[kt], KfH[nt]);
                MMA_BF16(s[nt], Qfh[kt], KfL[nt]);
                MMA_BF16(s[nt], Qfl[kt], KfH[nt]);
            }
        }

        // ---- online softmax (register + quad shuffle) ----
        float mx0 = s[0][0], mx1 = s[0][2];
#pragma unroll
        for (int nt = 0; nt < 8; nt++) {
            mx0 = fmaxf(mx0, fmaxf(s[nt][0], s[nt][1]));
            mx1 = fmaxf(mx1, fmaxf(s[nt][2], s[nt][3]));
        }
        mx0 = fmaxf(mx0, __shfl_xor_sync(0xffffffffu, mx0, 1));
        mx0 = fmaxf(mx0, __shfl_xor_sync(0xffffffffu, mx0, 2));
        mx1 = fmaxf(mx1, __shfl_xor_sync(0xffffffffu, mx1, 1));
        mx1 = fmaxf(mx1, __shfl_xor_sync(0xffffffffu, mx1, 2));

        float mn0 = fmaxf(m0, mx0), mn1 = fmaxf(m1, mx1);
        float a0 = __expf(m0 - mn0), a1 = __expf(m1 - mn1);
        m0 = mn0; m1 = mn1;

        float sum0 = 0.f, sum1 = 0.f;
#pragma unroll
        for (int nt = 0; nt < 8; nt++) {
            s[nt][0] = __expf(s[nt][0] - mn0);
            s[nt][1] = __expf(s[nt][1] - mn0);
            s[nt][2] = __expf(s[nt][2] - mn1);
            s[nt][3] = __expf(s[nt][3] - mn1);
            sum0 += s[nt][0] + s[nt][1];
            sum1 += s[nt][2] + s[nt][3];
        }
        sum0 += __shfl_xor_sync(0xffffffffu, sum0, 1);
        sum0 += __shfl_xor_sync(0xffffffffu, sum0, 2);
        sum1 += __shfl_xor_sync(0xffffffffu, sum1, 1);
        sum1 += __shfl_xor_sync(0xffffffffu, sum1, 2);
        l0 = l0 * a0 + sum0;
        l1 = l1 * a1 + sum1;

#pragma unroll
        for (int nt = 0; nt < 8; nt++) {
            O[nt][0] *= a0; O[nt][1] *= a0;
            O[nt][2] *= a1; O[nt][3] *= a1;
        }

        // ---- P fragments (hi/lo) ----
        uint32_t Pah[4][4], Pal[4][4];
#pragma unroll
        for (int kt = 0; kt < 4; kt++) {
            int e = 2 * kt, o = 2 * kt + 1;
            uint32_t h;
            h = bf2(s[e][0], s[e][1]);
            Pah[kt][0] = h;
            Pal[kt][0] = bf2(s[e][0] - bf_lo_f32(h), s[e][1] - bf_hi_f32(h));
            h = bf2(s[e][2], s[e][3]);
            Pah[kt][1] = h;
            Pal[kt][1] = bf2(s[e][2] - bf_lo_f32(h), s[e][3] - bf_hi_f32(h));
            h = bf2(s[o][0], s[o][1]);
            Pah[kt][2] = h;
            Pal[kt][2] = bf2(s[o][0] - bf_lo_f32(h), s[o][1] - bf_hi_f32(h));
            h = bf2(s[o][2], s[o][3]);
            Pah[kt][3] = h;
            Pal[kt][3] = bf2(s[o][2] - bf_lo_f32(h), s[o][3] - bf_hi_f32(h));
        }

        // ---- O += P V (bf16x3, V via ldmatrix.trans) ----
#pragma unroll
        for (int kt = 0; kt < 4; kt++) {
            uint32_t VfH[8][2], VfL[8][2];
#pragma unroll
            for (int p = 0; p < 4; p++) {
                uint32_t off = (uint32_t)(kt * 16 * QROW * 2) + (uint32_t)(p * 16 * 2);
                uint32_t r0, r1, r2, r3;
                LDSM_X4_T(r0, r1, r2, r3, vhB + off);
                VfH[2 * p][0] = r0; VfH[2 * p][1] = r1;
                VfH[2 * p + 1][0] = r2; VfH[2 * p + 1][1] = r3;
                LDSM_X4_T(r0, r1, r2, r3, vlB + off);
                VfL[2 * p][0] = r0; VfL[2 * p][1] = r1;
                VfL[2 * p + 1][0] = r2; VfL[2 * p + 1][1] = r3;
            }
#pragma unroll
            for (int nt = 0; nt < 8; nt++) {
                MMA_BF16(O[nt], Pah[kt], VfH[nt]);
                MMA_BF16(O[nt], Pah[kt], VfL[nt]);
                MMA_BF16(O[nt], Pal[kt], VfH[nt]);
            }
        }
        __syncthreads();
    }

    // ---- epilogue: normalize, split, write ctx bf16 planes ----
    float inv0 = 1.0f / l0, inv1 = 1.0f / l1;
    int b = bh >> 4, h = bh & 15;
    int r0g = q0 + w * 16 + gid;
    int r1g = r0g + 8;
#pragma unroll
    for (int nt = 0; nt < 8; nt++) {
        int d = nt * 8 + 2 * tig;
        size_t p0 = (size_t)(b * SEQ + r0g) * 512 + ((h * 64 + d) >> 1);
        size_t p1 = (size_t)(b * SEQ + r1g) * 512 + ((h * 64 + d) >> 1);
        float v0 = O[nt][0] * inv0, v1 = O[nt][1] * inv0;
        uint32_t hi = bf2(v0, v1);
        g_ch[p0] = hi;
        g_cl[p0] = bf2(v0 - bf_lo_f32(hi), v1 - bf_hi_f32(hi));
        v0 = O[nt][2] * inv1; v1 = O[nt][3] * inv1;
        hi = bf2(v0, v1);
        g_ch[p1] = hi;
        g_cl[p1] = bf2(v0 - bf_lo_f32(hi), v1 - bf_hi_f32(hi));
    }
}

// ---------------------------------------------------------------------------
extern "C" void kernel_launch(void* const* d_in, const int* in_sizes, int n_in,
                              void* d_out, int out_size)
{
    const float* query = (const float*)d_in[0];   // [4,2048,1024]
    const float* in_w  = (const float*)d_in[1];   // [3072,1024]
    const float* in_b  = (const float*)d_in[2];   // [3072]
    const float* out_w = (const float*)d_in[3];   // [1024,1024]
    const float* out_b = (const float*)d_in[4];   // [1024]
    float* out = (float*)d_out;                   // [4,2048,1024]

    cudaFuncSetAttribute(gemm_v2,
                         cudaFuncAttributeMaxDynamicSharedMemorySize, GEMM_SMEM2);
    cudaFuncSetAttribute(attn_v2,
                         cudaFuncAttributeMaxDynamicSharedMemorySize, ATTN_SMEM2);

    // 0) one-pass fp32 -> bf16 hi/lo plane splits
    conv_split<<<(M_ROWS * E_DIM / 4) / 256, 256>>>((const float4*)query, 0,
                                                    M_ROWS * E_DIM / 4);
    conv_split<<<(3 * E_DIM * E_DIM / 4) / 256, 256>>>((const float4*)in_w, 1,
                                                       3 * E_DIM * E_DIM / 4);
    conv_split<<<(E_DIM * E_DIM / 4) / 256, 256>>>((const float4*)out_w, 2,
                                                   E_DIM * E_DIM / 4);

    // 1) QKV projection + scatter to bf16 hi/lo planes (q scaled)
    gemm_v2<<<dim3(3 * E_DIM / 128, M_ROWS / 128), 256, GEMM_SMEM2>>>(
        in_b, nullptr, E_DIM, 3 * E_DIM, 0);

    // 2) Tensor-core flash attention -> ctx bf16 planes
    attn_v2<<<dim3(SEQ / 128, BH_TOT), 256, ATTN_SMEM2>>>();

    // 3) Output projection -> d_out (fp32)
    gemm_v2<<<dim3(E_DIM / 128, M_ROWS / 128), 256, GEMM_SMEM2>>>(
        out_b, out, E_DIM, E_DIM, 1);
}

// round 11
// speedup vs baseline: 4.0299x; 1.0212x over previous
#include <cuda_runtime.h>
#include <cstdint>

// Problem constants
#define E_DIM   1024
#define N_HEADS 16
#define HDIM    64
#define NB      4
#define SEQ     2048
#define BH_TOT  (NB * N_HEADS)   // 64
#define M_ROWS  (NB * SEQ)       // 8192
#define QKV_PAIRS (BH_TOT * SEQ * HDIM / 2)   // 4194304

// Scratch (device globals: no allocation allowed). All bf16x2-pair planes.
__device__ uint32_t g_ah[M_ROWS * E_DIM / 2], g_al[M_ROWS * E_DIM / 2];   // query
__device__ uint32_t g_wh[3 * E_DIM * E_DIM / 2], g_wl[3 * E_DIM * E_DIM / 2];
__device__ uint32_t g_oh[E_DIM * E_DIM / 2], g_ol[E_DIM * E_DIM / 2];
__device__ uint32_t g_ch[M_ROWS * E_DIM / 2], g_cl[M_ROWS * E_DIM / 2];   // ctx
__device__ uint32_t g_qh[QKV_PAIRS], g_ql[QKV_PAIRS];
__device__ uint32_t g_kh[QKV_PAIRS], g_kl[QKV_PAIRS];
__device__ uint32_t g_vh[QKV_PAIRS], g_vl[QKV_PAIRS];

// ---- helpers ---------------------------------------------------------------
__device__ __forceinline__ uint32_t smem_u32(const void* p) {
    uint32_t a;
    asm("{ .reg .u64 t; cvta.to.shared.u64 t, %1; cvt.u32.u64 %0, t; }"
        : "=r"(a) : "l"(p));
    return a;
}
__device__ __forceinline__ uint32_t bf2(float e0, float e1) {
    uint32_t r;
    asm("cvt.rn.bf16x2.f32 %0, %1, %2;" : "=r"(r) : "f"(e1), "f"(e0));
    return r;
}
__device__ __forceinline__ float bf_lo_f32(uint32_t p) {
    return __uint_as_float(p << 16);
}
__device__ __forceinline__ float bf_hi_f32(uint32_t p) {
    return __uint_as_float(p & 0xffff0000u);
}

__device__ __forceinline__ void cp16(uint32_t dst, const void* src) {
    asm volatile("cp.async.cg.shared.global [%0], [%1], 16;"
                 :: "r"(dst), "l"(src) : "memory");
}
#define CP_COMMIT asm volatile("cp.async.commit_group;" ::: "memory")
#define CP_WAIT0  asm volatile("cp.async.wait_group 0;" ::: "memory")

#define LDSM_X4(r0, r1, r2, r3, addr)                                        \
    asm volatile("ldmatrix.sync.aligned.m8n8.x4.shared.b16 "                 \
                 "{%0, %1, %2, %3}, [%4];"                                   \
                 : "=r"(r0), "=r"(r1), "=r"(r2), "=r"(r3) : "r"(addr))

#define LDSM_X4_T(r0, r1, r2, r3, addr)                                      \
    asm volatile("ldmatrix.sync.aligned.m8n8.x4.trans.shared.b16 "           \
                 "{%0, %1, %2, %3}, [%4];"                                   \
                 : "=r"(r0), "=r"(r1), "=r"(r2), "=r"(r3) : "r"(addr))

#define MMA_BF16(c, a, b)                                                    \
    asm volatile("mma.sync.aligned.m16n8k16.row.col.f32.bf16.bf16.f32 "      \
                 "{%0, %1, %2, %3}, {%4, %5, %6, %7}, {%8, %9}, "            \
                 "{%0, %1, %2, %3};"                                         \
                 : "+f"((c)[0]), "+f"((c)[1]), "+f"((c)[2]), "+f"((c)[3])    \
                 : "r"((a)[0]), "r"((a)[1]), "r"((a)[2]), "r"((a)[3]),       \
                   "r"((b)[0]), "r"((b)[1]))

// ===========================================================================
// One-pass fp32 -> bf16 hi/lo plane split.  which: 0=query 1=in_w 2=out_w
// ===========================================================================
__global__ __launch_bounds__(256) void conv_split(const float4* __restrict__ src,
                                                  int which, int n4)
{
    int i = blockIdx.x * 256 + threadIdx.x;
    if (i >= n4) return;
    uint2* hi = (uint2*)(which == 0 ? g_ah : (which == 1 ? g_wh : g_oh));
    uint2* lo = (uint2*)(which == 0 ? g_al : (which == 1 ? g_wl : g_ol));
    float4 a = src[i];
    uint32_t h01 = bf2(a.x, a.y), h23 = bf2(a.z, a.w);
    uint32_t l01 = bf2(a.x - bf_lo_f32(h01), a.y - bf_hi_f32(h01));
    uint32_t l23 = bf2(a.z - bf_lo_f32(h23), a.w - bf_hi_f32(h23));
    hi[i] = make_uint2(h01, h23);
    lo[i] = make_uint2(l01, l23);
}

// ===========================================================================
// bf16x3 tensor-core NT GEMM: pre-split operands, cp.async double buffer,
// ONE barrier per chunk (stage ch+1 issued inside compute(ch) shadow).
// which 0: A=g_ah/al, W=g_wh/wl, scatter-QKV epilogue (q *= 0.125)
// which 1: A=g_ch/cl, W=g_oh/ol, C-store epilogue
// ===========================================================================
#define SROW 40                        // bf16 per smem row (32 data + 8 pad)
#define GPLANE (128 * SROW * 2)        // 10240 B
#define GSTAGE (4 * GPLANE)            // 40960 B
#define GEMM_SMEM2 (2 * GSTAGE)        // 81920 B

__device__ __forceinline__ void stage_gemm(
    uint32_t stb, int t, int ch, int kd8,
    const uint4* Ah, const uint4* Al, const uint4* Wh, const uint4* Wl,
    int rbase, int cbase)
{
    const uint4* b0 = Ah + (size_t)rbase * kd8 + ch * 4;
    const uint4* b1 = Al + (size_t)rbase * kd8 + ch * 4;
    const uint4* b2 = Wh + (size_t)cbase * kd8 + ch * 4;
    const uint4* b3 = Wl + (size_t)cbase * kd8 + ch * 4;
#pragma unroll
    for (int half = 0; half < 2; half++) {
        int g = t + 256 * half;        // 0..511
        int row = g >> 2, c = g & 3;
        uint32_t d = stb + (uint32_t)(row * SROW * 2 + c * 16);
        size_t si = (size_t)row * kd8 + c;
        cp16(d + 0 * GPLANE, b0 + si);
        cp16(d + 1 * GPLANE, b1 + si);
        cp16(d + 2 * GPLANE, b2 + si);
        cp16(d + 3 * GPLANE, b3 + si);
    }
}

__global__ __launch_bounds__(256, 2) void gemm_v2(
    const float* __restrict__ bias, float* __restrict__ C,
    int K, int N, int which)
{
    extern __shared__ char smraw[];
    uint32_t sbase = smem_u32(smraw);

    const uint4* Ah = (const uint4*)(which == 0 ? g_ah : g_ch);
    const uint4* Al = (const uint4*)(which == 0 ? g_al : g_cl);
    const uint4* Wh = (const uint4*)(which == 0 ? g_wh : g_oh);
    const uint4* Wl = (const uint4*)(which == 0 ? g_wl : g_ol);

    int t    = threadIdx.x;
    int lane = t & 31;
    int wid  = t >> 5;
    int wm   = wid >> 2;
    int wn   = wid & 3;
    int gid  = lane >> 2;
    int tig  = lane & 3;

    int rbase = blockIdx.y * 128;
    int cbase = blockIdx.x * 128;
    int kd8   = K >> 3;

    uint32_t lm_off = (uint32_t)((lane & 15) * SROW + ((lane >> 4) << 3)) * 2;

    float acc[4][4][4];
#pragma unroll
    for (int i = 0; i < 4; i++)
#pragma unroll
        for (int j = 0; j < 4; j++)
#pragma unroll
            for (int r = 0; r < 4; r++) acc[i][j][r] = 0.f;

    const int nch = K / 32;
    stage_gemm(sbase, t, 0, kd8, Ah, Al, Wh, Wl, rbase, cbase);
    CP_COMMIT;

    for (int ch = 0; ch < nch; ch++) {
        CP_WAIT0;            // chunk ch landed (group committed last iter)
        __syncthreads();     // ...and everyone done reading buffer[(ch+1)&1]

        // stage next chunk in the shadow of compute(ch)
        if (ch + 1 < nch) {
            stage_gemm(sbase + ((ch + 1) & 1) * GSTAGE, t, ch + 1, kd8,
                       Ah, Al, Wh, Wl, rbase, cbase);
            CP_COMMIT;
        }

        uint32_t stb  = sbase + (ch & 1) * GSTAGE;
        uint32_t aHiB = stb + (uint32_t)(wm * 64 * SROW * 2) + lm_off;
        uint32_t aLoB = aHiB + GPLANE;
        uint32_t bHiB = stb + 2 * GPLANE + (uint32_t)(wn * 32 * SROW * 2) + lm_off;
        uint32_t bLoB = bHiB + GPLANE;

#pragma unroll
        for (int kk = 0; kk < 2; kk++) {
            uint32_t kb = (uint32_t)(kk * 16 * 2);
            uint32_t Ahf[4][4], Alf[4][4], Bh[4][2], Bl[4][2];
#pragma unroll
            for (int mt = 0; mt < 4; mt++) {
                uint32_t off = kb + (uint32_t)(mt * 16 * SROW * 2);
                LDSM_X4(Ahf[mt][0], Ahf[mt][1], Ahf[mt][2], Ahf[mt][3], aHiB + off);
                LDSM_X4(Alf[mt][0], Alf[mt][1], Alf[mt][2], Alf[mt][3], aLoB + off);
            }
#pragma unroll
            for (int nt2 = 0; nt2 < 2; nt2++) {
                uint32_t off = kb + (uint32_t)(nt2 * 16 * SROW * 2);
                uint32_t r0, r1, r2, r3;
                LDSM_X4(r0, r1, r2, r3, bHiB + off);
                Bh[nt2 * 2][0] = r0; Bh[nt2 * 2 + 1][0] = r1;
                Bh[nt2 * 2][1] = r2; Bh[nt2 * 2 + 1][1] = r3;
                LDSM_X4(r0, r1, r2, r3, bLoB + off);
                Bl[nt2 * 2][0] = r0; Bl[nt2 * 2 + 1][0] = r1;
                Bl[nt2 * 2][1] = r2; Bl[nt2 * 2 + 1][1] = r3;
            }
#pragma unroll
            for (int mt = 0; mt < 4; mt++)
#pragma unroll
                for (int nt = 0; nt < 4; nt++) {
                    MMA_BF16(acc[mt][nt], Ahf[mt], Bh[nt]);
                    MMA_BF16(acc[mt][nt], Ahf[mt], Bl[nt]);
                    MMA_BF16(acc[mt][nt], Alf[mt], Bh[nt]);
                }
        }
    }

#pragma unroll
    for (int mt = 0; mt < 4; mt++) {
#pragma unroll
        for (int nt = 0; nt < 4; nt++) {
            int n = cbase + wn * 32 + nt * 8 + 2 * tig;
            float bz0 = bias[n], bz1 = bias[n + 1];
#pragma unroll
            for (int half = 0; half < 2; half++) {
                int m = rbase + wm * 64 + mt * 16 + gid + half * 8;
                float v0 = acc[mt][nt][half * 2]     + bz0;
                float v1 = acc[mt][nt][half * 2 + 1] + bz1;
                if (which == 1) {
                    *(float2*)&C[(size_t)m * N + n] = make_float2(v0, v1);
                } else {
                    int part = n >> 10;
                    int rr   = n & 1023;
                    int h    = rr >> 6;
                    int d    = rr & 63;
                    int b    = m >> 11;
                    int tt   = m & 2047;
                    int pidx = (((b * N_HEADS + h) * SEQ + tt) * HDIM + d) >> 1;
                    if (part == 0) { v0 *= 0.125f; v1 *= 0.125f; }
                    uint32_t hi = bf2(v0, v1);
                    uint32_t lo = bf2(v0 - bf_lo_f32(hi), v1 - bf_hi_f32(hi));
                    if (part == 0)      { g_qh[pidx] = hi; g_ql[pidx] = lo; }
                    else if (part == 1) { g_kh[pidx] = hi; g_kl[pidx] = lo; }
                    else                { g_vh[pidx] = hi; g_vl[pidx] = lo; }
                }
            }
        }
    }
}

// ===========================================================================
// Tensor-core flash attention (bf16x3), cp.async double-buffered K/V,
// ONE barrier per K/V tile.  Block = 128 q-rows x (b,h); register softmax.
// ===========================================================================
#define QROW 72                         // 64 data + 8 pad bf16; 144 B rows
#define KVPLANE (64 * QROW * 2)         // 9216 B
#define KVSTAGE (4 * KVPLANE)           // 36864 B
#define ATTN_SMEM2 (2 * 128 * QROW * 2 + 2 * KVSTAGE)   // 110592 B

__device__ __forceinline__ void stage_kv(uint32_t stb, int t, int rowoff,
    const uint4* kh, const uint4* kl, const uint4* vh, const uint4* vl)
{
#pragma unroll
    for (int half = 0; half < 2; half++) {
        int g = t + 256 * half;         // 0..511
        int row = g >> 3, c = g & 7;
        uint32_t d = stb + (uint32_t)(row * QROW * 2 + c * 16);
        int si = rowoff + row * 8 + c;
        cp16(d + 0 * KVPLANE, kh + si);
        cp16(d + 1 * KVPLANE, kl + si);
        cp16(d + 2 * KVPLANE, vh + si);
        cp16(d + 3 * KVPLANE, vl + si);
    }
}

__global__ __launch_bounds__(256) void attn_v2()
{
    extern __shared__ char smraw[];
    uint16_t* Qh = (uint16_t*)smraw;                 // [128][QROW]
    uint16_t* Ql = Qh + 128 * QROW;
    uint32_t kvbase = smem_u32(smraw) + 2 * 128 * QROW * 2;

    int t    = threadIdx.x;
    int lane = t & 31;
    int w    = t >> 5;
    int gid  = lane >> 2;
    int tig  = lane & 3;
    int bh   = blockIdx.y;
    int q0   = blockIdx.x * 128;

    const uint4* gkh = (const uint4*)(g_kh + (size_t)bh * SEQ * 32);
    const uint4* gkl = (const uint4*)(g_kl + (size_t)bh * SEQ * 32);
    const uint4* gvh = (const uint4*)(g_vh + (size_t)bh * SEQ * 32);
    const uint4* gvl = (const uint4*)(g_vl + (size_t)bh * SEQ * 32);

    // prefetch K/V tile 0 while staging Q
    stage_kv(kvbase, t, 0, gkh, gkl, gvh, gvl);
    CP_COMMIT;

    const uint4* gqh = (const uint4*)(g_qh + ((size_t)bh * SEQ + q0) * 32);
    const uint4* gql = (const uint4*)(g_ql + ((size_t)bh * SEQ + q0) * 32);
#pragma unroll
    for (int i = 0; i < 4; i++) {
        int idx = t + 256 * i;
        int r   = idx >> 3;
        int c4  = (idx & 7) << 2;
        *(uint4*)&Qh[r * QROW + 2 * c4] = gqh[r * 8 + (idx & 7)];
        *(uint4*)&Ql[r * QROW + 2 * c4] = gql[r * 8 + (idx & 7)];
    }
    __syncthreads();

    uint32_t lmA = (uint32_t)((w * 16 + (lane & 15)) * QROW + ((lane >> 4) << 3)) * 2;
    uint32_t qhA = smem_u32(Qh) + lmA;
    uint32_t qlA = smem_u32(Ql) + lmA;
    uint32_t Qfh[4][4], Qfl[4][4];
#pragma unroll
    for (int kt = 0; kt < 4; kt++) {
        LDSM_X4(Qfh[kt][0], Qfh[kt][1], Qfh[kt][2], Qfh[kt][3], qhA + kt * 32);
        LDSM_X4(Qfl[kt][0], Qfl[kt][1], Qfl[kt][2], Qfl[kt][3], qlA + kt * 32);
    }

    uint32_t lmB = (uint32_t)((lane & 15) * QROW + ((lane >> 4) << 3)) * 2;

    float O[8][4];
#pragma unroll
    for (int nt = 0; nt < 8; nt++)
#pragma unroll
        for (int r = 0; r < 4; r++) O[nt][r] = 0.f;
    float m0 = -1e30f, m1 = -1e30f, l0 = 0.f, l1 = 0.f;

    const int ntiles = SEQ / 64;
    for (int jt = 0; jt < ntiles; jt++) {
        CP_WAIT0;           // tile jt landed
        __syncthreads();    // ...and all warps done reading buffer[(jt+1)&1]

        // stage next tile in the shadow of this tile's compute
        if (jt + 1 < ntiles) {
            stage_kv(kvbase + ((jt + 1) & 1) * KVSTAGE, t, (jt + 1) * 64 * 8,
                     gkh, gkl, gvh, gvl);
            CP_COMMIT;
        }

        uint32_t kvb = kvbase + (jt & 1) * KVSTAGE;
        uint32_t khB = kvb + lmB;
        uint32_t klB = khB + KVPLANE;
        uint32_t vhB = khB + 2 * KVPLANE;
        uint32_t vlB = khB + 3 * KVPLANE;

        // ---- S = Q K^T (bf16x3) ----
        float s[8][4];
#pragma unroll
        for (int nt = 0; nt < 8; nt++)
#pragma unroll
            for (int r = 0; r < 4; r++) s[nt][r] = 0.f;

#pragma unroll
        for (int kt = 0; kt < 4; kt++) {
            uint32_t KfH[8][2], KfL[8][2];
#pragma unroll
            for (int p = 0; p < 4; p++) {
                uint32_t off = (uint32_t)(p * 16 * QROW * 2) + kt * 32;
                uint32_t r0, r1, r2, r3;
                LDSM_X4(r0, r1, r2, r3, khB + off);
                KfH[2 * p][0] = r0; KfH[2 * p + 1][0] = r1;
                KfH[2 * p][1] = r2; KfH[2 * p + 1][1] = r3;
                LDSM_X4(r0, r1, r2, r3, klB + off);
                KfL[2 * p][0] = r0; KfL[2 * p + 1][0] = r1;
                KfL[2 * p][1] = r2; KfL[2 * p + 1][1] = r3;
            }
#pragma unroll
            for (int nt = 0; nt < 8; nt++) {
                MMA_BF16(s[nt], Qfh[kt], KfH[nt]);
                MMA_BF16(s[nt], Qfh[kt], KfL[nt]);
                MMA_BF16(s[nt], Qfl[kt], KfH[nt]);
            }
        }

        // ---- online softmax (register + quad shuffle) ----
        float mx0 = s[0][0], mx1 = s[0][2];
#pragma unroll
        for (int nt = 0; nt < 8; nt++) {
            mx0 = fmaxf(mx0, fmaxf(s[nt][0], s[nt][1]));
            mx1 = fmaxf(mx1, fmaxf(s[nt][2], s[nt][3]));
        }
        mx0 = fmaxf(mx0, __shfl_xor_sync(0xffffffffu, mx0, 1));
        mx0 = fmaxf(mx0, __shfl_xor_sync(0xffffffffu, mx0, 2));
        mx1 = fmaxf(mx1, __shfl_xor_sync(0xffffffffu, mx1, 1));
        mx1 = fmaxf(mx1, __shfl_xor_sync(0xffffffffu, mx1, 2));

        float mn0 = fmaxf(m0, mx0), mn1 = fmaxf(m1, mx1);
        float a0 = __expf(m0 - mn0), a1 = __expf(m1 - mn1);
        m0 = mn0; m1 = mn1;

        float sum0 = 0.f, sum1 = 0.f;
#pragma unroll
        for (int nt = 0; nt < 8; nt++) {
            s[nt][0] = __expf(s[nt][0] - mn0);
            s[nt][1] = __expf(s[nt][1] - mn0);
            s[nt][2] = __expf(s[nt][2] - mn1);
            s[nt][3] = __expf(s[nt][3] - mn1);
            sum0 += s[nt][0] + s[nt][1];
            sum1 += s[nt][2] + s[nt][3];
        }
        sum0 += __shfl_xor_sync(0xffffffffu, sum0, 1);
        sum0 += __shfl_xor_sync(0xffffffffu, sum0, 2);
        sum1 += __shfl_xor_sync(0xffffffffu, sum1, 1);
        sum1 += __shfl_xor_sync(0xffffffffu, sum1, 2);
        l0 = l0 * a0 + sum0;
        l1 = l1 * a1 + sum1;

#pragma unroll
        for (int nt = 0; nt < 8; nt++) {
            O[nt][0] *= a0; O[nt][1] *= a0;
            O[nt][2] *= a1; O[nt][3] *= a1;
        }

        // ---- P fragments (hi/lo) ----
        uint32_t Pah[4][4], Pal[4][4];
#pragma unroll
        for (int kt = 0; kt < 4; kt++) {
            int e = 2 * kt, o = 2 * kt + 1;
            uint32_t h;
            h = bf2(s[e][0], s[e][1]);
            Pah[kt][0] = h;
            Pal[kt][0] = bf2(s[e][0] - bf_lo_f32(h), s[e][1] - bf_hi_f32(h));
            h = bf2(s[e][2], s[e][3]);
            Pah[kt][1] = h;
            Pal[kt][1] = bf2(s[e][2] - bf_lo_f32(h), s[e][3] - bf_hi_f32(h));
            h = bf2(s[o][0], s[o][1]);
            Pah[kt][2] = h;
            Pal[kt][2] = bf2(s[o][0] - bf_lo_f32(h), s[o][1] - bf_hi_f32(h));
            h = bf2(s[o][2], s[o][3]);
            Pah[kt][3] = h;
            Pal[kt][3] = bf2(s[o][2] - bf_lo_f32(h), s[o][3] - bf_hi_f32(h));
        }

        // ---- O += P V (bf16x3, V via ldmatrix.trans) ----
#pragma unroll
        for (int kt = 0; kt < 4; kt++) {
            uint32_t VfH[8][2], VfL[8][2];
#pragma unroll
            for (int p = 0; p < 4; p++) {
                uint32_t off = (uint32_t)(kt * 16 * QROW * 2) + (uint32_t)(p * 16 * 2);
                uint32_t r0, r1, r2, r3;
                LDSM_X4_T(r0, r1, r2, r3, vhB + off);
                VfH[2 * p][0] = r0; VfH[2 * p][1] = r1;
                VfH[2 * p + 1][0] = r2; VfH[2 * p + 1][1] = r3;
                LDSM_X4_T(r0, r1, r2, r3, vlB + off);
                VfL[2 * p][0] = r0; VfL[2 * p][1] = r1;
                VfL[2 * p + 1][0] = r2; VfL[2 * p + 1][1] = r3;
            }
#pragma unroll
            for (int nt = 0; nt < 8; nt++) {
                MMA_BF16(O[nt], Pah[kt], VfH[nt]);
                MMA_BF16(O[nt], Pah[kt], VfL[nt]);
                MMA_BF16(O[nt], Pal[kt], VfH[nt]);
            }
        }
    }

    // ---- epilogue: normalize, split, write ctx bf16 planes ----
    float inv0 = 1.0f / l0, inv1 = 1.0f / l1;
    int b = bh >> 4, h = bh & 15;
    int r0g = q0 + w * 16 + gid;
    int r1g = r0g + 8;
#pragma unroll
    for (int nt = 0; nt < 8; nt++) {
        int d = nt * 8 + 2 * tig;
        size_t p0 = (size_t)(b * SEQ + r0g) * 512 + ((h * 64 + d) >> 1);
        size_t p1 = (size_t)(b * SEQ + r1g) * 512 + ((h * 64 + d) >> 1);
        float v0 = O[nt][0] * inv0, v1 = O[nt][1] * inv0;
        uint32_t hi = bf2(v0, v1);
        g_ch[p0] = hi;
        g_cl[p0] = bf2(v0 - bf_lo_f32(hi), v1 - bf_hi_f32(hi));
        v0 = O[nt][2] * inv1; v1 = O[nt][3] * inv1;
        hi = bf2(v0, v1);
        g_ch[p1] = hi;
        g_cl[p1] = bf2(v0 - bf_lo_f32(hi), v1 - bf_hi_f32(hi));
    }
}

// ---------------------------------------------------------------------------
extern "C" void kernel_launch(void* const* d_in, const int* in_sizes, int n_in,
                              void* d_out, int out_size)
{
    const float* query = (const float*)d_in[0];   // [4,2048,1024]
    const float* in_w  = (const float*)d_in[1];   // [3072,1024]
    const float* in_b  = (const float*)d_in[2];   // [3072]
    const float* out_w = (const float*)d_in[3];   // [1024,1024]
    const float* out_b = (const float*)d_in[4];   // [1024]
    float* out = (float*)d_out;                   // [4,2048,1024]

    cudaFuncSetAttribute(gemm_v2,
                         cudaFuncAttributeMaxDynamicSharedMemorySize, GEMM_SMEM2);
    cudaFuncSetAttribute(attn_v2,
                         cudaFuncAttributeMaxDynamicSharedMemorySize, ATTN_SMEM2);

    // 0) one-pass fp32 -> bf16 hi/lo plane splits
    conv_split<<<(M_ROWS * E_DIM / 4) / 256, 256>>>((const float4*)query, 0,
                                                    M_ROWS * E_DIM / 4);
    conv_split<<<(3 * E_DIM * E_DIM / 4) / 256, 256>>>((const float4*)in_w, 1,
                                                       3 * E_DIM * E_DIM / 4);
    conv_split<<<(E_DIM * E_DIM / 4) / 256, 256>>>((const float4*)out_w, 2,
                                                   E_DIM * E_DIM / 4);

    // 1) QKV projection + scatter to bf16 hi/lo planes (q scaled)
    gemm_v2<<<dim3(3 * E_DIM / 128, M_ROWS / 128), 256, GEMM_SMEM2>>>(
        in_b, nullptr, E_DIM, 3 * E_DIM, 0);

    // 2) Tensor-core flash attention -> ctx bf16 planes
    attn_v2<<<dim3(SEQ / 128, BH_TOT), 256, ATTN_SMEM2>>>();

    // 3) Output projection -> d_out (fp32)
    gemm_v2<<<dim3(E_DIM / 128, M_ROWS / 128), 256, GEMM_SMEM2>>>(
        out_b, out, E_DIM, E_DIM, 1);
}

// round 12
// speedup vs baseline: 4.1635x; 1.0332x over previous
#include <cuda_runtime.h>
#include <cstdint>

// Problem constants
#define E_DIM   1024
#define N_HEADS 16
#define HDIM    64
#define NB      4
#define SEQ     2048
#define BH_TOT  (NB * N_HEADS)   // 64
#define M_ROWS  (NB * SEQ)       // 8192
#define QKV_PAIRS (BH_TOT * SEQ * HDIM / 2)   // 4194304
#define QSCALE 0.18033688011112042f           // 0.125 * log2(e)

// Scratch (device globals: no allocation allowed). All bf16x2-pair planes.
__device__ uint32_t g_ah[M_ROWS * E_DIM / 2], g_al[M_ROWS * E_DIM / 2];   // query
__device__ uint32_t g_wh[3 * E_DIM * E_DIM / 2], g_wl[3 * E_DIM * E_DIM / 2];
__device__ uint32_t g_oh[E_DIM * E_DIM / 2], g_ol[E_DIM * E_DIM / 2];
__device__ uint32_t g_ch[M_ROWS * E_DIM / 2], g_cl[M_ROWS * E_DIM / 2];   // ctx
__device__ uint32_t g_qh[QKV_PAIRS], g_ql[QKV_PAIRS];
__device__ uint32_t g_kh[QKV_PAIRS], g_kl[QKV_PAIRS];
__device__ uint32_t g_vh[QKV_PAIRS], g_vl[QKV_PAIRS];

// ---- helpers ---------------------------------------------------------------
__device__ __forceinline__ uint32_t smem_u32(const void* p) {
    uint32_t a;
    asm("{ .reg .u64 t; cvta.to.shared.u64 t, %1; cvt.u32.u64 %0, t; }"
        : "=r"(a) : "l"(p));
    return a;
}
__device__ __forceinline__ uint32_t bf2(float e0, float e1) {
    uint32_t r;
    asm("cvt.rn.bf16x2.f32 %0, %1, %2;" : "=r"(r) : "f"(e1), "f"(e0));
    return r;
}
__device__ __forceinline__ float bf_lo_f32(uint32_t p) {
    return __uint_as_float(p << 16);
}
__device__ __forceinline__ float bf_hi_f32(uint32_t p) {
    return __uint_as_float(p & 0xffff0000u);
}

__device__ __forceinline__ void cp16(uint32_t dst, const void* src) {
    asm volatile("cp.async.cg.shared.global [%0], [%1], 16;"
                 :: "r"(dst), "l"(src) : "memory");
}
#define CP_COMMIT asm volatile("cp.async.commit_group;" ::: "memory")
#define CP_WAIT0  asm volatile("cp.async.wait_group 0;" ::: "memory")

#define LDSM_X4(r0, r1, r2, r3, addr)                                        \
    asm volatile("ldmatrix.sync.aligned.m8n8.x4.shared.b16 "                 \
                 "{%0, %1, %2, %3}, [%4];"                                   \
                 : "=r"(r0), "=r"(r1), "=r"(r2), "=r"(r3) : "r"(addr))

#define LDSM_X4_T(r0, r1, r2, r3, addr)                                      \
    asm volatile("ldmatrix.sync.aligned.m8n8.x4.trans.shared.b16 "           \
                 "{%0, %1, %2, %3}, [%4];"                                   \
                 : "=r"(r0), "=r"(r1), "=r"(r2), "=r"(r3) : "r"(addr))

#define MMA_BF16(c, a, b)                                                    \
    asm volatile("mma.sync.aligned.m16n8k16.row.col.f32.bf16.bf16.f32 "      \
                 "{%0, %1, %2, %3}, {%4, %5, %6, %7}, {%8, %9}, "            \
                 "{%0, %1, %2, %3};"                                         \
                 : "+f"((c)[0]), "+f"((c)[1]), "+f"((c)[2]), "+f"((c)[3])    \
                 : "r"((a)[0]), "r"((a)[1]), "r"((a)[2]), "r"((a)[3]),       \
                   "r"((b)[0]), "r"((b)[1]))

// ===========================================================================
// One-pass fp32 -> bf16 hi/lo plane split.  which: 0=query 1=in_w 2=out_w
// ===========================================================================
__global__ __launch_bounds__(256) void conv_split(const float4* __restrict__ src,
                                                  int which, int n4)
{
    int i = blockIdx.x * 256 + threadIdx.x;
    if (i >= n4) return;
    uint2* hi = (uint2*)(which == 0 ? g_ah : (which == 1 ? g_wh : g_oh));
    uint2* lo = (uint2*)(which == 0 ? g_al : (which == 1 ? g_wl : g_ol));
    float4 a = src[i];
    uint32_t h01 = bf2(a.x, a.y), h23 = bf2(a.z, a.w);
    uint32_t l01 = bf2(a.x - bf_lo_f32(h01), a.y - bf_hi_f32(h01));
    uint32_t l23 = bf2(a.z - bf_lo_f32(h23), a.w - bf_hi_f32(h23));
    hi[i] = make_uint2(h01, h23);
    lo[i] = make_uint2(l01, l23);
}

// ===========================================================================
// bf16x3 tensor-core NT GEMM; pass-major MMA ordering (16 independent MMAs
// per pass, per-acc order hh->hl->lh preserved => bit-identical results).
// ===========================================================================
#define SROW 40                        // bf16 per smem row (32 data + 8 pad)
#define GPLANE (128 * SROW * 2)        // 10240 B
#define GSTAGE (4 * GPLANE)            // 40960 B
#define GEMM_SMEM2 (2 * GSTAGE)        // 81920 B

__global__ __launch_bounds__(256, 2) void gemm_v2(
    const float* __restrict__ bias, float* __restrict__ C,
    int K, int N, int which)
{
    extern __shared__ char smraw[];
    uint32_t sbase = smem_u32(smraw);

    const uint4* Ah = (const uint4*)(which == 0 ? g_ah : g_ch);
    const uint4* Al = (const uint4*)(which == 0 ? g_al : g_cl);
    const uint4* Wh = (const uint4*)(which == 0 ? g_wh : g_oh);
    const uint4* Wl = (const uint4*)(which == 0 ? g_wl : g_ol);

    int t    = threadIdx.x;
    int lane = t & 31;
    int wid  = t >> 5;
    int wm   = wid >> 2;
    int wn   = wid & 3;
    int gid  = lane >> 2;
    int tig  = lane & 3;

    int rbase = blockIdx.y * 128;
    int cbase = blockIdx.x * 128;
    int kd8   = K >> 3;

    // ---- precomputed staging state (2 slots/thread, 4 planes each) ----
    size_t asi[2], wsi[2];
    uint32_t dso[2];
#pragma unroll
    for (int half = 0; half < 2; half++) {
        int g = t + 256 * half;        // 0..511
        int row = g >> 2, c = g & 3;
        asi[half] = (size_t)(rbase + row) * kd8 + c;
        wsi[half] = (size_t)(cbase + row) * kd8 + c;
        dso[half] = (uint32_t)(row * SROW * 2 + c * 16);
    }

    uint32_t lm_off = (uint32_t)((lane & 15) * SROW + ((lane >> 4) << 3)) * 2;

    float acc[4][4][4];
#pragma unroll
    for (int i = 0; i < 4; i++)
#pragma unroll
        for (int j = 0; j < 4; j++)
#pragma unroll
            for (int r = 0; r < 4; r++) acc[i][j][r] = 0.f;

    const int nch = K / 32;

#pragma unroll
    for (int half = 0; half < 2; half++) {
        uint32_t d = sbase + dso[half];
        cp16(d + 0 * GPLANE, Ah + asi[half]);
        cp16(d + 1 * GPLANE, Al + asi[half]);
        cp16(d + 2 * GPLANE, Wh + wsi[half]);
        cp16(d + 3 * GPLANE, Wl + wsi[half]);
    }
    CP_COMMIT;

    for (int ch = 0; ch < nch; ch++) {
        CP_WAIT0;
        __syncthreads();

        if (ch + 1 < nch) {
            uint32_t nb = sbase + ((ch + 1) & 1) * GSTAGE;
#pragma unroll
            for (int half = 0; half < 2; half++) {
                size_t sa = asi[half] + (size_t)(ch + 1) * 4;
                size_t sw = wsi[half] + (size_t)(ch + 1) * 4;
                uint32_t d = nb + dso[half];
                cp16(d + 0 * GPLANE, Ah + sa);
                cp16(d + 1 * GPLANE, Al + sa);
                cp16(d + 2 * GPLANE, Wh + sw);
                cp16(d + 3 * GPLANE, Wl + sw);
            }
            CP_COMMIT;
        }

        uint32_t stb  = sbase + (ch & 1) * GSTAGE;
        uint32_t aHiB = stb + (uint32_t)(wm * 64 * SROW * 2) + lm_off;
        uint32_t aLoB = aHiB + GPLANE;
        uint32_t bHiB = stb + 2 * GPLANE + (uint32_t)(wn * 32 * SROW * 2) + lm_off;
        uint32_t bLoB = bHiB + GPLANE;

#pragma unroll
        for (int kk = 0; kk < 2; kk++) {
            uint32_t kb = (uint32_t)(kk * 16 * 2);
            uint32_t Ahf[4][4], Alf[4][4], Bh[4][2], Bl[4][2];
#pragma unroll
            for (int mt = 0; mt < 4; mt++) {
                uint32_t off = kb + (uint32_t)(mt * 16 * SROW * 2);
                LDSM_X4(Ahf[mt][0], Ahf[mt][1], Ahf[mt][2], Ahf[mt][3], aHiB + off);
                LDSM_X4(Alf[mt][0], Alf[mt][1], Alf[mt][2], Alf[mt][3], aLoB + off);
            }
#pragma unroll
            for (int nt2 = 0; nt2 < 2; nt2++) {
                uint32_t off = kb + (uint32_t)(nt2 * 16 * SROW * 2);
                uint32_t r0, r1, r2, r3;
                LDSM_X4(r0, r1, r2, r3, bHiB + off);
                Bh[nt2 * 2][0] = r0; Bh[nt2 * 2 + 1][0] = r1;
                Bh[nt2 * 2][1] = r2; Bh[nt2 * 2 + 1][1] = r3;
                LDSM_X4(r0, r1, r2, r3, bLoB + off);
                Bl[nt2 * 2][0] = r0; Bl[nt2 * 2 + 1][0] = r1;
                Bl[nt2 * 2][1] = r2; Bl[nt2 * 2 + 1][1] = r3;
            }
            // pass-major: 16 independent MMAs per pass
#pragma unroll
            for (int mt = 0; mt < 4; mt++)
#pragma unroll
                for (int nt = 0; nt < 4; nt++)
                    MMA_BF16(acc[mt][nt], Ahf[mt], Bh[nt]);
#pragma unroll
            for (int mt = 0; mt < 4; mt++)
#pragma unroll
                for (int nt = 0; nt < 4; nt++)
                    MMA_BF16(acc[mt][nt], Ahf[mt], Bl[nt]);
#pragma unroll
            for (int mt = 0; mt < 4; mt++)
#pragma unroll
                for (int nt = 0; nt < 4; nt++)
                    MMA_BF16(acc[mt][nt], Alf[mt], Bh[nt]);
        }
    }

#pragma unroll
    for (int mt = 0; mt < 4; mt++) {
#pragma unroll
        for (int nt = 0; nt < 4; nt++) {
            int n = cbase + wn * 32 + nt * 8 + 2 * tig;
            float bz0 = bias[n], bz1 = bias[n + 1];
#pragma unroll
            for (int half = 0; half < 2; half++) {
                int m = rbase + wm * 64 + mt * 16 + gid + half * 8;
                float v0 = acc[mt][nt][half * 2]     + bz0;
                float v1 = acc[mt][nt][half * 2 + 1] + bz1;
                if (which == 1) {
                    *(float2*)&C[(size_t)m * N + n] = make_float2(v0, v1);
                } else {
                    int part = n >> 10;
                    int rr   = n & 1023;
                    int h    = rr >> 6;
                    int d    = rr & 63;
                    int b    = m >> 11;
                    int tt   = m & 2047;
                    int pidx = (((b * N_HEADS + h) * SEQ + tt) * HDIM + d) >> 1;
                    if (part == 0) { v0 *= QSCALE; v1 *= QSCALE; }  // fold log2e
                    uint32_t hi = bf2(v0, v1);
                    uint32_t lo = bf2(v0 - bf_lo_f32(hi), v1 - bf_hi_f32(hi));
                    if (part == 0)      { g_qh[pidx] = hi; g_ql[pidx] = lo; }
                    else if (part == 1) { g_kh[pidx] = hi; g_kl[pidx] = lo; }
                    else                { g_vh[pidx] = hi; g_vl[pidx] = lo; }
                }
            }
        }
    }
}

// ===========================================================================
// Tensor-core flash attention (bf16x3), exp2-based softmax (q pre-scaled by
// 0.125*log2e), pass-major MMA ordering, cp.async double-buffered K/V.
// ===========================================================================
#define QROW 72                         // 64 data + 8 pad bf16; 144 B rows
#define KVPLANE (64 * QROW * 2)         // 9216 B
#define KVSTAGE (4 * KVPLANE)           // 36864 B
#define ATTN_SMEM2 (2 * 128 * QROW * 2 + 2 * KVSTAGE)   // 110592 B

__global__ __launch_bounds__(256) void attn_v2()
{
    extern __shared__ char smraw[];
    uint16_t* Qh = (uint16_t*)smraw;                 // [128][QROW]
    uint16_t* Ql = Qh + 128 * QROW;
    uint32_t kvbase = smem_u32(smraw) + 2 * 128 * QROW * 2;

    int t    = threadIdx.x;
    int lane = t & 31;
    int w    = t >> 5;
    int gid  = lane >> 2;
    int tig  = lane & 3;
    int bh   = blockIdx.y;
    int q0   = blockIdx.x * 128;

    const uint4* gkh = (const uint4*)(g_kh + (size_t)bh * SEQ * 32);
    const uint4* gkl = (const uint4*)(g_kl + (size_t)bh * SEQ * 32);
    const uint4* gvh = (const uint4*)(g_vh + (size_t)bh * SEQ * 32);
    const uint4* gvl = (const uint4*)(g_vl + (size_t)bh * SEQ * 32);

    // precomputed staging state (2 slots/thread)
    int ksi[2];
    uint32_t kdo[2];
#pragma unroll
    for (int half = 0; half < 2; half++) {
        int g = t + 256 * half;
        int row = g >> 3, c = g & 7;
        ksi[half] = row * 8 + c;
        kdo[half] = (uint32_t)(row * QROW * 2 + c * 16);
    }

    // prefetch K/V tile 0 while staging Q
#pragma unroll
    for (int half = 0; half < 2; half++) {
        uint32_t d = kvbase + kdo[half];
        cp16(d + 0 * KVPLANE, gkh + ksi[half]);
        cp16(d + 1 * KVPLANE, gkl + ksi[half]);
        cp16(d + 2 * KVPLANE, gvh + ksi[half]);
        cp16(d + 3 * KVPLANE, gvl + ksi[half]);
    }
    CP_COMMIT;

    const uint4* gqh = (const uint4*)(g_qh + ((size_t)bh * SEQ + q0) * 32);
    const uint4* gql = (const uint4*)(g_ql + ((size_t)bh * SEQ + q0) * 32);
#pragma unroll
    for (int i = 0; i < 4; i++) {
        int idx = t + 256 * i;
        int r   = idx >> 3;
        int c4  = (idx & 7) << 2;
        *(uint4*)&Qh[r * QROW + 2 * c4] = gqh[r * 8 + (idx & 7)];
        *(uint4*)&Ql[r * QROW + 2 * c4] = gql[r * 8 + (idx & 7)];
    }
    __syncthreads();

    uint32_t lmA = (uint32_t)((w * 16 + (lane & 15)) * QROW + ((lane >> 4) << 3)) * 2;
    uint32_t qhA = smem_u32(Qh) + lmA;
    uint32_t qlA = smem_u32(Ql) + lmA;
    uint32_t Qfh[4][4], Qfl[4][4];
#pragma unroll
    for (int kt = 0; kt < 4; kt++) {
        LDSM_X4(Qfh[kt][0], Qfh[kt][1], Qfh[kt][2], Qfh[kt][3], qhA + kt * 32);
        LDSM_X4(Qfl[kt][0], Qfl[kt][1], Qfl[kt][2], Qfl[kt][3], qlA + kt * 32);
    }

    uint32_t lmB = (uint32_t)((lane & 15) * QROW + ((lane >> 4) << 3)) * 2;

    float O[8][4];
#pragma unroll
    for (int nt = 0; nt < 8; nt++)
#pragma unroll
        for (int r = 0; r < 4; r++) O[nt][r] = 0.f;
    float m0 = -1e30f, m1 = -1e30f, l0 = 0.f, l1 = 0.f;

    const int ntiles = SEQ / 64;
    for (int jt = 0; jt < ntiles; jt++) {
        CP_WAIT0;
        __syncthreads();

        if (jt + 1 < ntiles) {
            uint32_t nb = kvbase + ((jt + 1) & 1) * KVSTAGE;
            int roff = (jt + 1) * 512;
#pragma unroll
            for (int half = 0; half < 2; half++) {
                int si = ksi[half] + roff;
                uint32_t d = nb + kdo[half];
                cp16(d + 0 * KVPLANE, gkh + si);
                cp16(d + 1 * KVPLANE, gkl + si);
                cp16(d + 2 * KVPLANE, gvh + si);
                cp16(d + 3 * KVPLANE, gvl + si);
            }
            CP_COMMIT;
        }

        uint32_t kvb = kvbase + (jt & 1) * KVSTAGE;
        uint32_t khB = kvb + lmB;
        uint32_t klB = khB + KVPLANE;
        uint32_t vhB = khB + 2 * KVPLANE;
        uint32_t vlB = khB + 3 * KVPLANE;

        // ---- S = Q K^T (bf16x3, pass-major) ----
        float s[8][4];
#pragma unroll
        for (int nt = 0; nt < 8; nt++)
#pragma unroll
            for (int r = 0; r < 4; r++) s[nt][r] = 0.f;

#pragma unroll
        for (int kt = 0; kt < 4; kt++) {
            uint32_t KfH[8][2], KfL[8][2];
#pragma unroll
            for (int p = 0; p < 4; p++) {
                uint32_t off = (uint32_t)(p * 16 * QROW * 2) + kt * 32;
                uint32_t r0, r1, r2, r3;
                LDSM_X4(r0, r1, r2, r3, khB + off);
                KfH[2 * p][0] = r0; KfH[2 * p + 1][0] = r1;
                KfH[2 * p][1] = r2; KfH[2 * p + 1][1] = r3;
                LDSM_X4(r0, r1, r2, r3, klB + off);
                KfL[2 * p][0] = r0; KfL[2 * p + 1][0] = r1;
                KfL[2 * p][1] = r2; KfL[2 * p + 1][1] = r3;
            }
#pragma unroll
            for (int nt = 0; nt < 8; nt++)
                MMA_BF16(s[nt], Qfh[kt], KfH[nt]);
#pragma unroll
            for (int nt = 0; nt < 8; nt++)
                MMA_BF16(s[nt], Qfh[kt], KfL[nt]);
#pragma unroll
            for (int nt = 0; nt < 8; nt++)
                MMA_BF16(s[nt], Qfl[kt], KfH[nt]);
        }

        // ---- online softmax (exp2; q carries log2e) ----
        float mx0 = s[0][0], mx1 = s[0][2];
#pragma unroll
        for (int nt = 0; nt < 8; nt++) {
            mx0 = fmaxf(mx0, fmaxf(s[nt][0], s[nt][1]));
            mx1 = fmaxf(mx1, fmaxf(s[nt][2], s[nt][3]));
        }
        mx0 = fmaxf(mx0, __shfl_xor_sync(0xffffffffu, mx0, 1));
        mx0 = fmaxf(mx0, __shfl_xor_sync(0xffffffffu, mx0, 2));
        mx1 = fmaxf(mx1, __shfl_xor_sync(0xffffffffu, mx1, 1));
        mx1 = fmaxf(mx1, __shfl_xor_sync(0xffffffffu, mx1, 2));

        float mn0 = fmaxf(m0, mx0), mn1 = fmaxf(m1, mx1);
        float a0 = exp2f(m0 - mn0), a1 = exp2f(m1 - mn1);
        m0 = mn0; m1 = mn1;

        float sum0 = 0.f, sum1 = 0.f;
#pragma unroll
        for (int nt = 0; nt < 8; nt++) {
            s[nt][0] = exp2f(s[nt][0] - mn0);
            s[nt][1] = exp2f(s[nt][1] - mn0);
            s[nt][2] = exp2f(s[nt][2] - mn1);
            s[nt][3] = exp2f(s[nt][3] - mn1);
            sum0 += s[nt][0] + s[nt][1];
            sum1 += s[nt][2] + s[nt][3];
        }
        sum0 += __shfl_xor_sync(0xffffffffu, sum0, 1);
        sum0 += __shfl_xor_sync(0xffffffffu, sum0, 2);
        sum1 += __shfl_xor_sync(0xffffffffu, sum1, 1);
        sum1 += __shfl_xor_sync(0xffffffffu, sum1, 2);
        l0 = l0 * a0 + sum0;
        l1 = l1 * a1 + sum1;

#pragma unroll
        for (int nt = 0; nt < 8; nt++) {
            O[nt][0] *= a0; O[nt][1] *= a0;
            O[nt][2] *= a1; O[nt][3] *= a1;
        }

        // ---- P fragments (hi/lo) ----
        uint32_t Pah[4][4], Pal[4][4];
#pragma unroll
        for (int kt = 0; kt < 4; kt++) {
            int e = 2 * kt, o = 2 * kt + 1;
            uint32_t h;
            h = bf2(s[e][0], s[e][1]);
            Pah[kt][0] = h;
            Pal[kt][0] = bf2(s[e][0] - bf_lo_f32(h), s[e][1] - bf_hi_f32(h));
            h = bf2(s[e][2], s[e][3]);
            Pah[kt][1] = h;
            Pal[kt][1] = bf2(s[e][2] - bf_lo_f32(h), s[e][3] - bf_hi_f32(h));
            h = bf2(s[o][0], s[o][1]);
            Pah[kt][2] = h;
            Pal[kt][2] = bf2(s[o][0] - bf_lo_f32(h), s[o][1] - bf_hi_f32(h));
            h = bf2(s[o][2], s[o][3]);
            Pah[kt][3] = h;
            Pal[kt][3] = bf2(s[o][2] - bf_lo_f32(h), s[o][3] - bf_hi_f32(h));
        }

        // ---- O += P V (bf16x3, pass-major, V via ldmatrix.trans) ----
#pragma unroll
        for (int kt = 0; kt < 4; kt++) {
            uint32_t VfH[8][2], VfL[8][2];
#pragma unroll
            for (int p = 0; p < 4; p++) {
                uint32_t off = (uint32_t)(kt * 16 * QROW * 2) + (uint32_t)(p * 16 * 2);
                uint32_t r0, r1, r2, r3;
                LDSM_X4_T(r0, r1, r2, r3, vhB + off);
                VfH[2 * p][0] = r0; VfH[2 * p][1] = r1;
                VfH[2 * p + 1][0] = r2; VfH[2 * p + 1][1] = r3;
                LDSM_X4_T(r0, r1, r2, r3, vlB + off);
                VfL[2 * p][0] = r0; VfL[2 * p][1] = r1;
                VfL[2 * p + 1][0] = r2; VfL[2 * p + 1][1] = r3;
            }
#pragma unroll
            for (int nt = 0; nt < 8; nt++)
                MMA_BF16(O[nt], Pah[kt], VfH[nt]);
#pragma unroll
            for (int nt = 0; nt < 8; nt++)
                MMA_BF16(O[nt], Pah[kt], VfL[nt]);
#pragma unroll
            for (int nt = 0; nt < 8; nt++)
                MMA_BF16(O[nt], Pal[kt], VfH[nt]);
        }
    }

    // ---- epilogue: normalize, split, write ctx bf16 planes ----
    float inv0 = 1.0f / l0, inv1 = 1.0f / l1;
    int b = bh >> 4, h = bh & 15;
    int r0g = q0 + w * 16 + gid;
    int r1g = r0g + 8;
#pragma unroll
    for (int nt = 0; nt < 8; nt++) {
        int d = nt * 8 + 2 * tig;
        size_t p0 = (size_t)(b * SEQ + r0g) * 512 + ((h * 64 + d) >> 1);
        size_t p1 = (size_t)(b * SEQ + r1g) * 512 + ((h * 64 + d) >> 1);
        float v0 = O[nt][0] * inv0, v1 = O[nt][1] * inv0;
        uint32_t hi = bf2(v0, v1);
        g_ch[p0] = hi;
        g_cl[p0] = bf2(v0 - bf_lo_f32(hi), v1 - bf_hi_f32(hi));
        v0 = O[nt][2] * inv1; v1 = O[nt][3] * inv1;
        hi = bf2(v0, v1);
        g_ch[p1] = hi;
        g_cl[p1] = bf2(v0 - bf_lo_f32(hi), v1 - bf_hi_f32(hi));
    }
}

// ---------------------------------------------------------------------------
extern "C" void kernel_launch(void* const* d_in, const int* in_sizes, int n_in,
                              void* d_out, int out_size)
{
    const float* query = (const float*)d_in[0];   // [4,2048,1024]
    const float* in_w  = (const float*)d_in[1];   // [3072,1024]
    const float* in_b  = (const float*)d_in[2];   // [3072]
    const float* out_w = (const float*)d_in[3];   // [1024,1024]
    const float* out_b = (const float*)d_in[4];   // [1024]
    float* out = (float*)d_out;                   // [4,2048,1024]

    cudaFuncSetAttribute(gemm_v2,
                         cudaFuncAttributeMaxDynamicSharedMemorySize, GEMM_SMEM2);
    cudaFuncSetAttribute(attn_v2,
                         cudaFuncAttributeMaxDynamicSharedMemorySize, ATTN_SMEM2);

    // 0) one-pass fp32 -> bf16 hi/lo plane splits
    conv_split<<<(M_ROWS * E_DIM / 4) / 256, 256>>>((const float4*)query, 0,
                                                    M_ROWS * E_DIM / 4);
    conv_split<<<(3 * E_DIM * E_DIM / 4) / 256, 256>>>((const float4*)in_w, 1,
                                                       3 * E_DIM * E_DIM / 4);
    conv_split<<<(E_DIM * E_DIM / 4) / 256, 256>>>((const float4*)out_w, 2,
                                                   E_DIM * E_DIM / 4);

    // 1) QKV projection + scatter to bf16 hi/lo planes (q scaled w/ log2e)
    gemm_v2<<<dim3(3 * E_DIM / 128, M_ROWS / 128), 256, GEMM_SMEM2>>>(
        in_b, nullptr, E_DIM, 3 * E_DIM, 0);

    // 2) Tensor-core flash attention -> ctx bf16 planes
    attn_v2<<<dim3(SEQ / 128, BH_TOT), 256, ATTN_SMEM2>>>();

    // 3) Output projection -> d_out (fp32)
    gemm_v2<<<dim3(E_DIM / 128, M_ROWS / 128), 256, GEMM_SMEM2>>>(
        out_b, out, E_DIM, E_DIM, 1);
}

// round 13
// speedup vs baseline: 5.7480x; 1.3806x over previous
#include <cuda_runtime.h>
#include <cuda_fp16.h>
#include <cstdint>

// Problem constants
#define E_DIM   1024
#define N_HEADS 16
#define HDIM    64
#define NB      4
#define SEQ     2048
#define BH_TOT  (NB * N_HEADS)   // 64
#define M_ROWS  (NB * SEQ)       // 8192
#define QKV_PAIRS (BH_TOT * SEQ * HDIM / 2)   // 4194304
#define QSCALE 0.18033688011112042f           // 0.125 * log2(e)

// Scratch (device globals). fp16x2-pair planes.
// A-side operands keep hi+lo; B-side operands hi only.
__device__ uint32_t g_ah[M_ROWS * E_DIM / 2], g_al[M_ROWS * E_DIM / 2];  // query
__device__ uint32_t g_wh[3 * E_DIM * E_DIM / 2];                          // in_w hi
__device__ uint32_t g_oh[E_DIM * E_DIM / 2];                              // out_w hi
__device__ uint32_t g_ch[M_ROWS * E_DIM / 2], g_cl[M_ROWS * E_DIM / 2];  // ctx
__device__ uint32_t g_qh[QKV_PAIRS], g_ql[QKV_PAIRS];
__device__ uint32_t g_kh[QKV_PAIRS];                                      // K hi
__device__ uint32_t g_vh[QKV_PAIRS];                                      // V hi

// ---- helpers ---------------------------------------------------------------
__device__ __forceinline__ uint32_t smem_u32(const void* p) {
    uint32_t a;
    asm("{ .reg .u64 t; cvta.to.shared.u64 t, %1; cvt.u32.u64 %0, t; }"
        : "=r"(a) : "l"(p));
    return a;
}
// pack two f32 -> f16x2 (e0 in low 16 bits)
__device__ __forceinline__ uint32_t h2pack(float e0, float e1) {
    __half2 h = __floats2half2_rn(e0, e1);
    return *reinterpret_cast<uint32_t*>(&h);
}
__device__ __forceinline__ float h_lo(uint32_t p) {
    return __half2float(__ushort_as_half((unsigned short)(p & 0xffffu)));
}
__device__ __forceinline__ float h_hi(uint32_t p) {
    return __half2float(__ushort_as_half((unsigned short)(p >> 16)));
}

__device__ __forceinline__ void cp16(uint32_t dst, const void* src) {
    asm volatile("cp.async.cg.shared.global [%0], [%1], 16;"
                 :: "r"(dst), "l"(src) : "memory");
}
#define CP_COMMIT asm volatile("cp.async.commit_group;" ::: "memory")
#define CP_WAIT0  asm volatile("cp.async.wait_group 0;" ::: "memory")

#define LDSM_X4(r0, r1, r2, r3, addr)                                        \
    asm volatile("ldmatrix.sync.aligned.m8n8.x4.shared.b16 "                 \
                 "{%0, %1, %2, %3}, [%4];"                                   \
                 : "=r"(r0), "=r"(r1), "=r"(r2), "=r"(r3) : "r"(addr))

#define LDSM_X4_T(r0, r1, r2, r3, addr)                                      \
    asm volatile("ldmatrix.sync.aligned.m8n8.x4.trans.shared.b16 "           \
                 "{%0, %1, %2, %3}, [%4];"                                   \
                 : "=r"(r0), "=r"(r1), "=r"(r2), "=r"(r3) : "r"(addr))

#define MMA_F16(c, a, b)                                                     \
    asm volatile("mma.sync.aligned.m16n8k16.row.col.f32.f16.f16.f32 "        \
                 "{%0, %1, %2, %3}, {%4, %5, %6, %7}, {%8, %9}, "            \
                 "{%0, %1, %2, %3};"                                         \
                 : "+f"((c)[0]), "+f"((c)[1]), "+f"((c)[2]), "+f"((c)[3])    \
                 : "r"((a)[0]), "r"((a)[1]), "r"((a)[2]), "r"((a)[3]),       \
                   "r"((b)[0]), "r"((b)[1]))

// ===========================================================================
// One-pass fp32 -> fp16 split.  which 0: query (hi+lo)  1: in_w (hi)  2: out_w (hi)
// ===========================================================================
__global__ __launch_bounds__(256) void conv_split(const float4* __restrict__ src,
                                                  int which, int n4)
{
    int i = blockIdx.x * 256 + threadIdx.x;
    if (i >= n4) return;
    float4 a = src[i];
    uint32_t h01 = h2pack(a.x, a.y), h23 = h2pack(a.z, a.w);
    if (which == 0) {
        ((uint2*)g_ah)[i] = make_uint2(h01, h23);
        uint32_t l01 = h2pack(a.x - h_lo(h01), a.y - h_hi(h01));
        uint32_t l23 = h2pack(a.z - h_lo(h23), a.w - h_hi(h23));
        ((uint2*)g_al)[i] = make_uint2(l01, l23);
    } else if (which == 1) {
        ((uint2*)g_wh)[i] = make_uint2(h01, h23);
    } else {
        ((uint2*)g_oh)[i] = make_uint2(h01, h23);
    }
}

// ===========================================================================
// fp16x2 tensor-core NT GEMM: (Ah+Al)*Bh, 2 MMA passes, cp.async dbl buffer.
// which 0: A=g_ah/al, W=g_wh, QKV-scatter epilogue (q *= QSCALE)
// which 1: A=g_ch/cl, W=g_oh, C-store epilogue
// ===========================================================================
#define SROW 40                        // f16 per smem row (32 data + 8 pad)
#define GPLANE (128 * SROW * 2)        // 10240 B
#define GSTAGE (3 * GPLANE)            // 30720 B  (A_hi, A_lo, B_hi)
#define GEMM_SMEM2 (2 * GSTAGE)        // 61440 B

__global__ __launch_bounds__(256, 2) void gemm_v2(
    const float* __restrict__ bias, float* __restrict__ C,
    int K, int N, int which)
{
    extern __shared__ char smraw[];
    uint32_t sbase = smem_u32(smraw);

    const uint4* Ah = (const uint4*)(which == 0 ? g_ah : g_ch);
    const uint4* Al = (const uint4*)(which == 0 ? g_al : g_cl);
    const uint4* Wh = (const uint4*)(which == 0 ? g_wh : g_oh);

    int t    = threadIdx.x;
    int lane = t & 31;
    int wid  = t >> 5;
    int wm   = wid >> 2;
    int wn   = wid & 3;
    int gid  = lane >> 2;
    int tig  = lane & 3;

    int rbase = blockIdx.y * 128;
    int cbase = blockIdx.x * 128;
    int kd8   = K >> 3;

    size_t asi[2], wsi[2];
    uint32_t dso[2];
#pragma unroll
    for (int half = 0; half < 2; half++) {
        int g = t + 256 * half;        // 0..511
        int row = g >> 2, c = g & 3;
        asi[half] = (size_t)(rbase + row) * kd8 + c;
        wsi[half] = (size_t)(cbase + row) * kd8 + c;
        dso[half] = (uint32_t)(row * SROW * 2 + c * 16);
    }

    uint32_t lm_off = (uint32_t)((lane & 15) * SROW + ((lane >> 4) << 3)) * 2;

    float acc[4][4][4];
#pragma unroll
    for (int i = 0; i < 4; i++)
#pragma unroll
        for (int j = 0; j < 4; j++)
#pragma unroll
            for (int r = 0; r < 4; r++) acc[i][j][r] = 0.f;

    const int nch = K / 32;

#pragma unroll
    for (int half = 0; half < 2; half++) {
        uint32_t d = sbase + dso[half];
        cp16(d + 0 * GPLANE, Ah + asi[half]);
        cp16(d + 1 * GPLANE, Al + asi[half]);
        cp16(d + 2 * GPLANE, Wh + wsi[half]);
    }
    CP_COMMIT;

    for (int ch = 0; ch < nch; ch++) {
        CP_WAIT0;
        __syncthreads();

        if (ch + 1 < nch) {
            uint32_t nb = sbase + ((ch + 1) & 1) * GSTAGE;
#pragma unroll
            for (int half = 0; half < 2; half++) {
                size_t sa = asi[half] + (size_t)(ch + 1) * 4;
                size_t sw = wsi[half] + (size_t)(ch + 1) * 4;
                uint32_t d = nb + dso[half];
                cp16(d + 0 * GPLANE, Ah + sa);
                cp16(d + 1 * GPLANE, Al + sa);
                cp16(d + 2 * GPLANE, Wh + sw);
            }
            CP_COMMIT;
        }

        uint32_t stb  = sbase + (ch & 1) * GSTAGE;
        uint32_t aHiB = stb + (uint32_t)(wm * 64 * SROW * 2) + lm_off;
        uint32_t aLoB = aHiB + GPLANE;
        uint32_t bHiB = stb + 2 * GPLANE + (uint32_t)(wn * 32 * SROW * 2) + lm_off;

#pragma unroll
        for (int kk = 0; kk < 2; kk++) {
            uint32_t kb = (uint32_t)(kk * 16 * 2);
            uint32_t Ahf[4][4], Alf[4][4], Bh[4][2];
#pragma unroll
            for (int mt = 0; mt < 4; mt++) {
                uint32_t off = kb + (uint32_t)(mt * 16 * SROW * 2);
                LDSM_X4(Ahf[mt][0], Ahf[mt][1], Ahf[mt][2], Ahf[mt][3], aHiB + off);
                LDSM_X4(Alf[mt][0], Alf[mt][1], Alf[mt][2], Alf[mt][3], aLoB + off);
            }
#pragma unroll
            for (int nt2 = 0; nt2 < 2; nt2++) {
                uint32_t off = kb + (uint32_t)(nt2 * 16 * SROW * 2);
                uint32_t r0, r1, r2, r3;
                LDSM_X4(r0, r1, r2, r3, bHiB + off);
                Bh[nt2 * 2][0] = r0; Bh[nt2 * 2 + 1][0] = r1;
                Bh[nt2 * 2][1] = r2; Bh[nt2 * 2 + 1][1] = r3;
            }
            // pass 1: Ah*Bh (16 independent), pass 2: Al*Bh
#pragma unroll
            for (int mt = 0; mt < 4; mt++)
#pragma unroll
                for (int nt = 0; nt < 4; nt++)
                    MMA_F16(acc[mt][nt], Ahf[mt], Bh[nt]);
#pragma unroll
            for (int mt = 0; mt < 4; mt++)
#pragma unroll
                for (int nt = 0; nt < 4; nt++)
                    MMA_F16(acc[mt][nt], Alf[mt], Bh[nt]);
        }
    }

#pragma unroll
    for (int mt = 0; mt < 4; mt++) {
#pragma unroll
        for (int nt = 0; nt < 4; nt++) {
            int n = cbase + wn * 32 + nt * 8 + 2 * tig;
            float bz0 = bias[n], bz1 = bias[n + 1];
#pragma unroll
            for (int half = 0; half < 2; half++) {
                int m = rbase + wm * 64 + mt * 16 + gid + half * 8;
                float v0 = acc[mt][nt][half * 2]     + bz0;
                float v1 = acc[mt][nt][half * 2 + 1] + bz1;
                if (which == 1) {
                    *(float2*)&C[(size_t)m * N + n] = make_float2(v0, v1);
                } else {
                    int part = n >> 10;
                    int rr   = n & 1023;
                    int h    = rr >> 6;
                    int d    = rr & 63;
                    int b    = m >> 11;
                    int tt   = m & 2047;
                    int pidx = (((b * N_HEADS + h) * SEQ + tt) * HDIM + d) >> 1;
                    if (part == 0) {
                        v0 *= QSCALE; v1 *= QSCALE;
                        uint32_t hi = h2pack(v0, v1);
                        g_qh[pidx] = hi;
                        g_ql[pidx] = h2pack(v0 - h_lo(hi), v1 - h_hi(hi));
                    } else if (part == 1) {
                        g_kh[pidx] = h2pack(v0, v1);
                    } else {
                        g_vh[pidx] = h2pack(v0, v1);
                    }
                }
            }
        }
    }
}

// ===========================================================================
// fp16x2 tensor-core flash attention: (Qh+Ql)*Kh, (Ph+Pl)*Vh; exp2 softmax;
// cp.async double-buffered single-plane K/V.
// ===========================================================================
#define QROW 72                         // 64 data + 8 pad f16; 144 B rows
#define KVPLANE (64 * QROW * 2)         // 9216 B
#define KVSTAGE (2 * KVPLANE)           // 18432 B  (K_hi, V_hi)
#define ATTN_SMEM2 (2 * 128 * QROW * 2 + 2 * KVSTAGE)   // 73728 B

__global__ __launch_bounds__(256) void attn_v2()
{
    extern __shared__ char smraw[];
    uint16_t* Qh = (uint16_t*)smraw;                 // [128][QROW]
    uint16_t* Ql = Qh + 128 * QROW;
    uint32_t kvbase = smem_u32(smraw) + 2 * 128 * QROW * 2;

    int t    = threadIdx.x;
    int lane = t & 31;
    int w    = t >> 5;
    int gid  = lane >> 2;
    int tig  = lane & 3;
    int bh   = blockIdx.y;
    int q0   = blockIdx.x * 128;

    const uint4* gkh = (const uint4*)(g_kh + (size_t)bh * SEQ * 32);
    const uint4* gvh = (const uint4*)(g_vh + (size_t)bh * SEQ * 32);

    int ksi[2];
    uint32_t kdo[2];
#pragma unroll
    for (int half = 0; half < 2; half++) {
        int g = t + 256 * half;
        int row = g >> 3, c = g & 7;
        ksi[half] = row * 8 + c;
        kdo[half] = (uint32_t)(row * QROW * 2 + c * 16);
    }

    // prefetch K/V tile 0 while staging Q
#pragma unroll
    for (int half = 0; half < 2; half++) {
        uint32_t d = kvbase + kdo[half];
        cp16(d + 0 * KVPLANE, gkh + ksi[half]);
        cp16(d + 1 * KVPLANE, gvh + ksi[half]);
    }
    CP_COMMIT;

    const uint4* gqh = (const uint4*)(g_qh + ((size_t)bh * SEQ + q0) * 32);
    const uint4* gql = (const uint4*)(g_ql + ((size_t)bh * SEQ + q0) * 32);
#pragma unroll
    for (int i = 0; i < 4; i++) {
        int idx = t + 256 * i;
        int r   = idx >> 3;
        int c4  = (idx & 7) << 2;
        *(uint4*)&Qh[r * QROW + 2 * c4] = gqh[r * 8 + (idx & 7)];
        *(uint4*)&Ql[r * QROW + 2 * c4] = gql[r * 8 + (idx & 7)];
    }
    __syncthreads();

    uint32_t lmA = (uint32_t)((w * 16 + (lane & 15)) * QROW + ((lane >> 4) << 3)) * 2;
    uint32_t qhA = smem_u32(Qh) + lmA;
    uint32_t qlA = smem_u32(Ql) + lmA;
    uint32_t Qfh[4][4], Qfl[4][4];
#pragma unroll
    for (int kt = 0; kt < 4; kt++) {
        LDSM_X4(Qfh[kt][0], Qfh[kt][1], Qfh[kt][2], Qfh[kt][3], qhA + kt * 32);
        LDSM_X4(Qfl[kt][0], Qfl[kt][1], Qfl[kt][2], Qfl[kt][3], qlA + kt * 32);
    }

    uint32_t lmB = (uint32_t)((lane & 15) * QROW + ((lane >> 4) << 3)) * 2;

    float O[8][4];
#pragma unroll
    for (int nt = 0; nt < 8; nt++)
#pragma unroll
        for (int r = 0; r < 4; r++) O[nt][r] = 0.f;
    float m0 = -1e30f, m1 = -1e30f, l0 = 0.f, l1 = 0.f;

    const int ntiles = SEQ / 64;
    for (int jt = 0; jt < ntiles; jt++) {
        CP_WAIT0;
        __syncthreads();

        if (jt + 1 < ntiles) {
            uint32_t nb = kvbase + ((jt + 1) & 1) * KVSTAGE;
            int roff = (jt + 1) * 512;
#pragma unroll
            for (int half = 0; half < 2; half++) {
                int si = ksi[half] + roff;
                uint32_t d = nb + kdo[half];
                cp16(d + 0 * KVPLANE, gkh + si);
                cp16(d + 1 * KVPLANE, gvh + si);
            }
            CP_COMMIT;
        }

        uint32_t kvb = kvbase + (jt & 1) * KVSTAGE;
        uint32_t khB = kvb + lmB;
        uint32_t vhB = kvb + KVPLANE + lmB;

        // ---- S = Q K^T (fp16x2, 2 passes) ----
        float s[8][4];
#pragma unroll
        for (int nt = 0; nt < 8; nt++)
#pragma unroll
            for (int r = 0; r < 4; r++) s[nt][r] = 0.f;

#pragma unroll
        for (int kt = 0; kt < 4; kt++) {
            uint32_t KfH[8][2];
#pragma unroll
            for (int p = 0; p < 4; p++) {
                uint32_t off = (uint32_t)(p * 16 * QROW * 2) + kt * 32;
                uint32_t r0, r1, r2, r3;
                LDSM_X4(r0, r1, r2, r3, khB + off);
                KfH[2 * p][0] = r0; KfH[2 * p + 1][0] = r1;
                KfH[2 * p][1] = r2; KfH[2 * p + 1][1] = r3;
            }
#pragma unroll
            for (int nt = 0; nt < 8; nt++)
                MMA_F16(s[nt], Qfh[kt], KfH[nt]);
#pragma unroll
            for (int nt = 0; nt < 8; nt++)
                MMA_F16(s[nt], Qfl[kt], KfH[nt]);
        }

        // ---- online softmax (exp2; q carries log2e) ----
        float mx0 = s[0][0], mx1 = s[0][2];
#pragma unroll
        for (int nt = 0; nt < 8; nt++) {
            mx0 = fmaxf(mx0, fmaxf(s[nt][0], s[nt][1]));
            mx1 = fmaxf(mx1, fmaxf(s[nt][2], s[nt][3]));
        }
        mx0 = fmaxf(mx0, __shfl_xor_sync(0xffffffffu, mx0, 1));
        mx0 = fmaxf(mx0, __shfl_xor_sync(0xffffffffu, mx0, 2));
        mx1 = fmaxf(mx1, __shfl_xor_sync(0xffffffffu, mx1, 1));
        mx1 = fmaxf(mx1, __shfl_xor_sync(0xffffffffu, mx1, 2));

        float mn0 = fmaxf(m0, mx0), mn1 = fmaxf(m1, mx1);
        float a0 = exp2f(m0 - mn0), a1 = exp2f(m1 - mn1);
        m0 = mn0; m1 = mn1;

        float sum0 = 0.f, sum1 = 0.f;
#pragma unroll
        for (int nt = 0; nt < 8; nt++) {
            s[nt][0] = exp2f(s[nt][0] - mn0);
            s[nt][1] = exp2f(s[nt][1] - mn0);
            s[nt][2] = exp2f(s[nt][2] - mn1);
            s[nt][3] = exp2f(s[nt][3] - mn1);
            sum0 += s[nt][0] + s[nt][1];
            sum1 += s[nt][2] + s[nt][3];
        }
        sum0 += __shfl_xor_sync(0xffffffffu, sum0, 1);
        sum0 += __shfl_xor_sync(0xffffffffu, sum0, 2);
        sum1 += __shfl_xor_sync(0xffffffffu, sum1, 1);
        sum1 += __shfl_xor_sync(0xffffffffu, sum1, 2);
        l0 = l0 * a0 + sum0;
        l1 = l1 * a1 + sum1;

#pragma unroll
        for (int nt = 0; nt < 8; nt++) {
            O[nt][0] *= a0; O[nt][1] *= a0;
            O[nt][2] *= a1; O[nt][3] *= a1;
        }

        // ---- P fragments (fp16 hi/lo) ----
        uint32_t Pah[4][4], Pal[4][4];
#pragma unroll
        for (int kt = 0; kt < 4; kt++) {
            int e = 2 * kt, o = 2 * kt + 1;
            uint32_t h;
            h = h2pack(s[e][0], s[e][1]);
            Pah[kt][0] = h;
            Pal[kt][0] = h2pack(s[e][0] - h_lo(h), s[e][1] - h_hi(h));
            h = h2pack(s[e][2], s[e][3]);
            Pah[kt][1] = h;
            Pal[kt][1] = h2pack(s[e][2] - h_lo(h), s[e][3] - h_hi(h));
            h = h2pack(s[o][0], s[o][1]);
            Pah[kt][2] = h;
            Pal[kt][2] = h2pack(s[o][0] - h_lo(h), s[o][1] - h_hi(h));
            h = h2pack(s[o][2], s[o][3]);
            Pah[kt][3] = h;
            Pal[kt][3] = h2pack(s[o][2] - h_lo(h), s[o][3] - h_hi(h));
        }

        // ---- O += P V (fp16x2, 2 passes, V via ldmatrix.trans) ----
#pragma unroll
        for (int kt = 0; kt < 4; kt++) {
            uint32_t VfH[8][2];
#pragma unroll
            for (int p = 0; p < 4; p++) {
                uint32_t off = (uint32_t)(kt * 16 * QROW * 2) + (uint32_t)(p * 16 * 2);
                uint32_t r0, r1, r2, r3;
                LDSM_X4_T(r0, r1, r2, r3, vhB + off);
                VfH[2 * p][0] = r0; VfH[2 * p][1] = r1;
                VfH[2 * p + 1][0] = r2; VfH[2 * p + 1][1] = r3;
            }
#pragma unroll
            for (int nt = 0; nt < 8; nt++)
                MMA_F16(O[nt], Pah[kt], VfH[nt]);
#pragma unroll
            for (int nt = 0; nt < 8; nt++)
                MMA_F16(O[nt], Pal[kt], VfH[nt]);
        }
    }

    // ---- epilogue: normalize, split, write ctx fp16 planes ----
    float inv0 = 1.0f / l0, inv1 = 1.0f / l1;
    int b = bh >> 4, h = bh & 15;
    int r0g = q0 + w * 16 + gid;
    int r1g = r0g + 8;
#pragma unroll
    for (int nt = 0; nt < 8; nt++) {
        int d = nt * 8 + 2 * tig;
        size_t p0 = (size_t)(b * SEQ + r0g) * 512 + ((h * 64 + d) >> 1);
        size_t p1 = (size_t)(b * SEQ + r1g) * 512 + ((h * 64 + d) >> 1);
        float v0 = O[nt][0] * inv0, v1 = O[nt][1] * inv0;
        uint32_t hi = h2pack(v0, v1);
        g_ch[p0] = hi;
        g_cl[p0] = h2pack(v0 - h_lo(hi), v1 - h_hi(hi));
        v0 = O[nt][2] * inv1; v1 = O[nt][3] * inv1;
        hi = h2pack(v0, v1);
        g_ch[p1] = hi;
        g_cl[p1] = h2pack(v0 - h_lo(hi), v1 - h_hi(hi));
    }
}

// ---------------------------------------------------------------------------
extern "C" void kernel_launch(void* const* d_in, const int* in_sizes, int n_in,
                              void* d_out, int out_size)
{
    const float* query = (const float*)d_in[0];   // [4,2048,1024]
    const float* in_w  = (const float*)d_in[1];   // [3072,1024]
    const float* in_b  = (const float*)d_in[2];   // [3072]
    const float* out_w = (const float*)d_in[3];   // [1024,1024]
    const float* out_b = (const float*)d_in[4];   // [1024]
    float* out = (float*)d_out;                   // [4,2048,1024]

    cudaFuncSetAttribute(gemm_v2,
                         cudaFuncAttributeMaxDynamicSharedMemorySize, GEMM_SMEM2);
    cudaFuncSetAttribute(attn_v2,
                         cudaFuncAttributeMaxDynamicSharedMemorySize, ATTN_SMEM2);

    // 0) one-pass fp32 -> fp16 plane splits
    conv_split<<<(M_ROWS * E_DIM / 4) / 256, 256>>>((const float4*)query, 0,
                                                    M_ROWS * E_DIM / 4);
    conv_split<<<(3 * E_DIM * E_DIM / 4) / 256, 256>>>((const float4*)in_w, 1,
                                                       3 * E_DIM * E_DIM / 4);
    conv_split<<<(E_DIM * E_DIM / 4) / 256, 256>>>((const float4*)out_w, 2,
                                                   E_DIM * E_DIM / 4);

    // 1) QKV projection + scatter (q scaled w/ log2e)
    gemm_v2<<<dim3(3 * E_DIM / 128, M_ROWS / 128), 256, GEMM_SMEM2>>>(
        in_b, nullptr, E_DIM, 3 * E_DIM, 0);

    // 2) Tensor-core flash attention -> ctx fp16 planes
    attn_v2<<<dim3(SEQ / 128, BH_TOT), 256, ATTN_SMEM2>>>();

    // 3) Output projection -> d_out (fp32)
    gemm_v2<<<dim3(E_DIM / 128, M_ROWS / 128), 256, GEMM_SMEM2>>>(
        out_b, out, E_DIM, E_DIM, 1);
}

// round 14
// speedup vs baseline: 6.6510x; 1.1571x over previous
#include <cuda_runtime.h>
#include <cuda_fp16.h>
#include <cstdint>

// Problem constants
#define E_DIM   1024
#define N_HEADS 16
#define HDIM    64
#define NB      4
#define SEQ     2048
#define BH_TOT  (NB * N_HEADS)   // 64
#define M_ROWS  (NB * SEQ)       // 8192
#define QKV_PAIRS (BH_TOT * SEQ * HDIM / 2)   // 4194304
#define QSCALE 0.18033688011112042f           // 0.125 * log2(e)

// Scratch (device globals). fp16x2-pair planes.
// A-side operands keep hi+lo; B-side operands hi only.
__device__ uint32_t g_ah[M_ROWS * E_DIM / 2], g_al[M_ROWS * E_DIM / 2];  // query
__device__ uint32_t g_wh[3 * E_DIM * E_DIM / 2];                          // in_w hi
__device__ uint32_t g_oh[E_DIM * E_DIM / 2];                              // out_w hi
__device__ uint32_t g_ch[M_ROWS * E_DIM / 2], g_cl[M_ROWS * E_DIM / 2];  // ctx
__device__ uint32_t g_qh[QKV_PAIRS], g_ql[QKV_PAIRS];
__device__ uint32_t g_kh[QKV_PAIRS];                                      // K hi
__device__ uint32_t g_vh[QKV_PAIRS];                                      // V hi

// ---- helpers ---------------------------------------------------------------
__device__ __forceinline__ uint32_t smem_u32(const void* p) {
    uint32_t a;
    asm("{ .reg .u64 t; cvta.to.shared.u64 t, %1; cvt.u32.u64 %0, t; }"
        : "=r"(a) : "l"(p));
    return a;
}
// pack two f32 -> f16x2 (e0 in low 16 bits)
__device__ __forceinline__ uint32_t h2pack(float e0, float e1) {
    __half2 h = __floats2half2_rn(e0, e1);
    return *reinterpret_cast<uint32_t*>(&h);
}
__device__ __forceinline__ float h_lo(uint32_t p) {
    return __half2float(__ushort_as_half((unsigned short)(p & 0xffffu)));
}
__device__ __forceinline__ float h_hi(uint32_t p) {
    return __half2float(__ushort_as_half((unsigned short)(p >> 16)));
}

__device__ __forceinline__ void cp16(uint32_t dst, const void* src) {
    asm volatile("cp.async.cg.shared.global [%0], [%1], 16;"
                 :: "r"(dst), "l"(src) : "memory");
}
#define CP_COMMIT asm volatile("cp.async.commit_group;" ::: "memory")
#define CP_WAIT0  asm volatile("cp.async.wait_group 0;" ::: "memory")

#define LDSM_X4(r0, r1, r2, r3, addr)                                        \
    asm volatile("ldmatrix.sync.aligned.m8n8.x4.shared.b16 "                 \
                 "{%0, %1, %2, %3}, [%4];"                                   \
                 : "=r"(r0), "=r"(r1), "=r"(r2), "=r"(r3) : "r"(addr))

#define LDSM_X4_T(r0, r1, r2, r3, addr)                                      \
    asm volatile("ldmatrix.sync.aligned.m8n8.x4.trans.shared.b16 "           \
                 "{%0, %1, %2, %3}, [%4];"                                   \
                 : "=r"(r0), "=r"(r1), "=r"(r2), "=r"(r3) : "r"(addr))

#define MMA_F16(c, a, b)                                                     \
    asm volatile("mma.sync.aligned.m16n8k16.row.col.f32.f16.f16.f32 "        \
                 "{%0, %1, %2, %3}, {%4, %5, %6, %7}, {%8, %9}, "            \
                 "{%0, %1, %2, %3};"                                         \
                 : "+f"((c)[0]), "+f"((c)[1]), "+f"((c)[2]), "+f"((c)[3])    \
                 : "r"((a)[0]), "r"((a)[1]), "r"((a)[2]), "r"((a)[3]),       \
                   "r"((b)[0]), "r"((b)[1]))

// ===========================================================================
// One-pass fp32 -> fp16 split.  which 0: query (hi+lo)  1: in_w (hi)  2: out_w (hi)
// ===========================================================================
__global__ __launch_bounds__(256) void conv_split(const float4* __restrict__ src,
                                                  int which, int n4)
{
    int i = blockIdx.x * 256 + threadIdx.x;
    if (i >= n4) return;
    float4 a = src[i];
    uint32_t h01 = h2pack(a.x, a.y), h23 = h2pack(a.z, a.w);
    if (which == 0) {
        ((uint2*)g_ah)[i] = make_uint2(h01, h23);
        uint32_t l01 = h2pack(a.x - h_lo(h01), a.y - h_hi(h01));
        uint32_t l23 = h2pack(a.z - h_lo(h23), a.w - h_hi(h23));
        ((uint2*)g_al)[i] = make_uint2(l01, l23);
    } else if (which == 1) {
        ((uint2*)g_wh)[i] = make_uint2(h01, h23);
    } else {
        ((uint2*)g_oh)[i] = make_uint2(h01, h23);
    }
}

// ===========================================================================
// fp16x2 tensor-core NT GEMM: (Ah+Al)*Bh, 2 MMA passes, cp.async dbl buffer.
// which 0: A=g_ah/al, W=g_wh, QKV-scatter epilogue (q *= QSCALE)
// which 1: A=g_ch/cl, W=g_oh, C-store epilogue
// ===========================================================================
#define SROW 40                        // f16 per smem row (32 data + 8 pad)
#define GPLANE (128 * SROW * 2)        // 10240 B
#define GSTAGE (3 * GPLANE)            // 30720 B  (A_hi, A_lo, B_hi)
#define GEMM_SMEM2 (2 * GSTAGE)        // 61440 B

__global__ __launch_bounds__(256, 2) void gemm_v2(
    const float* __restrict__ bias, float* __restrict__ C,
    int K, int N, int which)
{
    extern __shared__ char smraw[];
    uint32_t sbase = smem_u32(smraw);

    const uint4* Ah = (const uint4*)(which == 0 ? g_ah : g_ch);
    const uint4* Al = (const uint4*)(which == 0 ? g_al : g_cl);
    const uint4* Wh = (const uint4*)(which == 0 ? g_wh : g_oh);

    int t    = threadIdx.x;
    int lane = t & 31;
    int wid  = t >> 5;
    int wm   = wid >> 2;
    int wn   = wid & 3;
    int gid  = lane >> 2;
    int tig  = lane & 3;

    int rbase = blockIdx.y * 128;
    int cbase = blockIdx.x * 128;
    int kd8   = K >> 3;

    size_t asi[2], wsi[2];
    uint32_t dso[2];
#pragma unroll
    for (int half = 0; half < 2; half++) {
        int g = t + 256 * half;        // 0..511
        int row = g >> 2, c = g & 3;
        asi[half] = (size_t)(rbase + row) * kd8 + c;
        wsi[half] = (size_t)(cbase + row) * kd8 + c;
        dso[half] = (uint32_t)(row * SROW * 2 + c * 16);
    }

    uint32_t lm_off = (uint32_t)((lane & 15) * SROW + ((lane >> 4) << 3)) * 2;

    float acc[4][4][4];
#pragma unroll
    for (int i = 0; i < 4; i++)
#pragma unroll
        for (int j = 0; j < 4; j++)
#pragma unroll
            for (int r = 0; r < 4; r++) acc[i][j][r] = 0.f;

    const int nch = K / 32;

#pragma unroll
    for (int half = 0; half < 2; half++) {
        uint32_t d = sbase + dso[half];
        cp16(d + 0 * GPLANE, Ah + asi[half]);
        cp16(d + 1 * GPLANE, Al + asi[half]);
        cp16(d + 2 * GPLANE, Wh + wsi[half]);
    }
    CP_COMMIT;

    for (int ch = 0; ch < nch; ch++) {
        CP_WAIT0;
        __syncthreads();

        if (ch + 1 < nch) {
            uint32_t nb = sbase + ((ch + 1) & 1) * GSTAGE;
#pragma unroll
            for (int half = 0; half < 2; half++) {
                size_t sa = asi[half] + (size_t)(ch + 1) * 4;
                size_t sw = wsi[half] + (size_t)(ch + 1) * 4;
                uint32_t d = nb + dso[half];
                cp16(d + 0 * GPLANE, Ah + sa);
                cp16(d + 1 * GPLANE, Al + sa);
                cp16(d + 2 * GPLANE, Wh + sw);
            }
            CP_COMMIT;
        }

        uint32_t stb  = sbase + (ch & 1) * GSTAGE;
        uint32_t aHiB = stb + (uint32_t)(wm * 64 * SROW * 2) + lm_off;
        uint32_t aLoB = aHiB + GPLANE;
        uint32_t bHiB = stb + 2 * GPLANE + (uint32_t)(wn * 32 * SROW * 2) + lm_off;

#pragma unroll
        for (int kk = 0; kk < 2; kk++) {
            uint32_t kb = (uint32_t)(kk * 16 * 2);
            uint32_t Ahf[4][4], Alf[4][4], Bh[4][2];
#pragma unroll
            for (int mt = 0; mt < 4; mt++) {
                uint32_t off = kb + (uint32_t)(mt * 16 * SROW * 2);
                LDSM_X4(Ahf[mt][0], Ahf[mt][1], Ahf[mt][2], Ahf[mt][3], aHiB + off);
                LDSM_X4(Alf[mt][0], Alf[mt][1], Alf[mt][2], Alf[mt][3], aLoB + off);
            }
#pragma unroll
            for (int nt2 = 0; nt2 < 2; nt2++) {
                uint32_t off = kb + (uint32_t)(nt2 * 16 * SROW * 2);
                uint32_t r0, r1, r2, r3;
                LDSM_X4(r0, r1, r2, r3, bHiB + off);
                Bh[nt2 * 2][0] = r0; Bh[nt2 * 2 + 1][0] = r1;
                Bh[nt2 * 2][1] = r2; Bh[nt2 * 2 + 1][1] = r3;
            }
            // pass 1: Ah*Bh (16 independent), pass 2: Al*Bh
#pragma unroll
            for (int mt = 0; mt < 4; mt++)
#pragma unroll
                for (int nt = 0; nt < 4; nt++)
                    MMA_F16(acc[mt][nt], Ahf[mt], Bh[nt]);
#pragma unroll
            for (int mt = 0; mt < 4; mt++)
#pragma unroll
                for (int nt = 0; nt < 4; nt++)
                    MMA_F16(acc[mt][nt], Alf[mt], Bh[nt]);
        }
    }

#pragma unroll
    for (int mt = 0; mt < 4; mt++) {
#pragma unroll
        for (int nt = 0; nt < 4; nt++) {
            int n = cbase + wn * 32 + nt * 8 + 2 * tig;
            float bz0 = bias[n], bz1 = bias[n + 1];
#pragma unroll
            for (int half = 0; half < 2; half++) {
                int m = rbase + wm * 64 + mt * 16 + gid + half * 8;
                float v0 = acc[mt][nt][half * 2]     + bz0;
                float v1 = acc[mt][nt][half * 2 + 1] + bz1;
                if (which == 1) {
                    *(float2*)&C[(size_t)m * N + n] = make_float2(v0, v1);
                } else {
                    int part = n >> 10;
                    int rr   = n & 1023;
                    int h    = rr >> 6;
                    int d    = rr & 63;
                    int b    = m >> 11;
                    int tt   = m & 2047;
                    int pidx = (((b * N_HEADS + h) * SEQ + tt) * HDIM + d) >> 1;
                    if (part == 0) {
                        v0 *= QSCALE; v1 *= QSCALE;
                        uint32_t hi = h2pack(v0, v1);
                        g_qh[pidx] = hi;
                        g_ql[pidx] = h2pack(v0 - h_lo(hi), v1 - h_hi(hi));
                    } else if (part == 1) {
                        g_kh[pidx] = h2pack(v0, v1);
                    } else {
                        g_vh[pidx] = h2pack(v0, v1);
                    }
                }
            }
        }
    }
}

// ===========================================================================
// fp16x2 tensor-core flash attention: (Qh+Ql)*Kh, Ph*Vh (3 passes total);
// exp2 softmax; cp.async double-buffered single-plane K/V; 2 CTAs/SM.
// ===========================================================================
#define QROW 72                         // 64 data + 8 pad f16; 144 B rows
#define KVPLANE (64 * QROW * 2)         // 9216 B
#define KVSTAGE (2 * KVPLANE)           // 18432 B  (K_hi, V_hi)
#define ATTN_SMEM2 (2 * 128 * QROW * 2 + 2 * KVSTAGE)   // 73728 B

__global__ __launch_bounds__(256, 2) void attn_v2()
{
    extern __shared__ char smraw[];
    uint16_t* Qh = (uint16_t*)smraw;                 // [128][QROW]
    uint16_t* Ql = Qh + 128 * QROW;
    uint32_t kvbase = smem_u32(smraw) + 2 * 128 * QROW * 2;

    int t    = threadIdx.x;
    int lane = t & 31;
    int w    = t >> 5;
    int gid  = lane >> 2;
    int tig  = lane & 3;
    int bh   = blockIdx.y;
    int q0   = blockIdx.x * 128;

    const uint4* gkh = (const uint4*)(g_kh + (size_t)bh * SEQ * 32);
    const uint4* gvh = (const uint4*)(g_vh + (size_t)bh * SEQ * 32);

    int ksi[2];
    uint32_t kdo[2];
#pragma unroll
    for (int half = 0; half < 2; half++) {
        int g = t + 256 * half;
        int row = g >> 3, c = g & 7;
        ksi[half] = row * 8 + c;
        kdo[half] = (uint32_t)(row * QROW * 2 + c * 16);
    }

    // prefetch K/V tile 0 while staging Q
#pragma unroll
    for (int half = 0; half < 2; half++) {
        uint32_t d = kvbase + kdo[half];
        cp16(d + 0 * KVPLANE, gkh + ksi[half]);
        cp16(d + 1 * KVPLANE, gvh + ksi[half]);
    }
    CP_COMMIT;

    const uint4* gqh = (const uint4*)(g_qh + ((size_t)bh * SEQ + q0) * 32);
    const uint4* gql = (const uint4*)(g_ql + ((size_t)bh * SEQ + q0) * 32);
#pragma unroll
    for (int i = 0; i < 4; i++) {
        int idx = t + 256 * i;
        int r   = idx >> 3;
        int c4  = (idx & 7) << 2;
        *(uint4*)&Qh[r * QROW + 2 * c4] = gqh[r * 8 + (idx & 7)];
        *(uint4*)&Ql[r * QROW + 2 * c4] = gql[r * 8 + (idx & 7)];
    }
    __syncthreads();

    uint32_t lmA = (uint32_t)((w * 16 + (lane & 15)) * QROW + ((lane >> 4) << 3)) * 2;
    uint32_t qhA = smem_u32(Qh) + lmA;
    uint32_t qlA = smem_u32(Ql) + lmA;
    uint32_t Qfh[4][4], Qfl[4][4];
#pragma unroll
    for (int kt = 0; kt < 4; kt++) {
        LDSM_X4(Qfh[kt][0], Qfh[kt][1], Qfh[kt][2], Qfh[kt][3], qhA + kt * 32);
        LDSM_X4(Qfl[kt][0], Qfl[kt][1], Qfl[kt][2], Qfl[kt][3], qlA + kt * 32);
    }

    uint32_t lmB = (uint32_t)((lane & 15) * QROW + ((lane >> 4) << 3)) * 2;

    float O[8][4];
#pragma unroll
    for (int nt = 0; nt < 8; nt++)
#pragma unroll
        for (int r = 0; r < 4; r++) O[nt][r] = 0.f;
    float m0 = -1e30f, m1 = -1e30f, l0 = 0.f, l1 = 0.f;

    const int ntiles = SEQ / 64;
    for (int jt = 0; jt < ntiles; jt++) {
        CP_WAIT0;
        __syncthreads();

        if (jt + 1 < ntiles) {
            uint32_t nb = kvbase + ((jt + 1) & 1) * KVSTAGE;
            int roff = (jt + 1) * 512;
#pragma unroll
            for (int half = 0; half < 2; half++) {
                int si = ksi[half] + roff;
                uint32_t d = nb + kdo[half];
                cp16(d + 0 * KVPLANE, gkh + si);
                cp16(d + 1 * KVPLANE, gvh + si);
            }
            CP_COMMIT;
        }

        uint32_t kvb = kvbase + (jt & 1) * KVSTAGE;
        uint32_t khB = kvb + lmB;
        uint32_t vhB = kvb + KVPLANE + lmB;

        // ---- S = Q K^T (fp16x2, 2 passes) ----
        float s[8][4];
#pragma unroll
        for (int nt = 0; nt < 8; nt++)
#pragma unroll
            for (int r = 0; r < 4; r++) s[nt][r] = 0.f;

#pragma unroll
        for (int kt = 0; kt < 4; kt++) {
            uint32_t KfH[8][2];
#pragma unroll
            for (int p = 0; p < 4; p++) {
                uint32_t off = (uint32_t)(p * 16 * QROW * 2) + kt * 32;
                uint32_t r0, r1, r2, r3;
                LDSM_X4(r0, r1, r2, r3, khB + off);
                KfH[2 * p][0] = r0; KfH[2 * p + 1][0] = r1;
                KfH[2 * p][1] = r2; KfH[2 * p + 1][1] = r3;
            }
#pragma unroll
            for (int nt = 0; nt < 8; nt++)
                MMA_F16(s[nt], Qfh[kt], KfH[nt]);
#pragma unroll
            for (int nt = 0; nt < 8; nt++)
                MMA_F16(s[nt], Qfl[kt], KfH[nt]);
        }

        // ---- online softmax (exp2; q carries log2e) ----
        float mx0 = s[0][0], mx1 = s[0][2];
#pragma unroll
        for (int nt = 0; nt < 8; nt++) {
            mx0 = fmaxf(mx0, fmaxf(s[nt][0], s[nt][1]));
            mx1 = fmaxf(mx1, fmaxf(s[nt][2], s[nt][3]));
        }
        mx0 = fmaxf(mx0, __shfl_xor_sync(0xffffffffu, mx0, 1));
        mx0 = fmaxf(mx0, __shfl_xor_sync(0xffffffffu, mx0, 2));
        mx1 = fmaxf(mx1, __shfl_xor_sync(0xffffffffu, mx1, 1));
        mx1 = fmaxf(mx1, __shfl_xor_sync(0xffffffffu, mx1, 2));

        float mn0 = fmaxf(m0, mx0), mn1 = fmaxf(m1, mx1);
        float a0 = exp2f(m0 - mn0), a1 = exp2f(m1 - mn1);
        m0 = mn0; m1 = mn1;

        float sum0 = 0.f, sum1 = 0.f;
#pragma unroll
        for (int nt = 0; nt < 8; nt++) {
            s[nt][0] = exp2f(s[nt][0] - mn0);
            s[nt][1] = exp2f(s[nt][1] - mn0);
            s[nt][2] = exp2f(s[nt][2] - mn1);
            s[nt][3] = exp2f(s[nt][3] - mn1);
            sum0 += s[nt][0] + s[nt][1];
            sum1 += s[nt][2] + s[nt][3];
        }
        sum0 += __shfl_xor_sync(0xffffffffu, sum0, 1);
        sum0 += __shfl_xor_sync(0xffffffffu, sum0, 2);
        sum1 += __shfl_xor_sync(0xffffffffu, sum1, 1);
        sum1 += __shfl_xor_sync(0xffffffffu, sum1, 2);
        l0 = l0 * a0 + sum0;
        l1 = l1 * a1 + sum1;

#pragma unroll
        for (int nt = 0; nt < 8; nt++) {
            O[nt][0] *= a0; O[nt][1] *= a0;
            O[nt][2] *= a1; O[nt][3] *= a1;
        }

        // ---- P fragments (fp16 hi only; lo-pass dropped: P in [0,1],
        //      residual <=2^-12 abs, random-signed, averaged by softmax) ----
        uint32_t Pah[4][4];
#pragma unroll
        for (int kt = 0; kt < 4; kt++) {
            int e = 2 * kt, o = 2 * kt + 1;
            Pah[kt][0] = h2pack(s[e][0], s[e][1]);
            Pah[kt][1] = h2pack(s[e][2], s[e][3]);
            Pah[kt][2] = h2pack(s[o][0], s[o][1]);
            Pah[kt][3] = h2pack(s[o][2], s[o][3]);
        }

        // ---- O += P V (fp16, 1 pass, V via ldmatrix.trans) ----
#pragma unroll
        for (int kt = 0; kt < 4; kt++) {
            uint32_t VfH[8][2];
#pragma unroll
            for (int p = 0; p < 4; p++) {
                uint32_t off = (uint32_t)(kt * 16 * QROW * 2) + (uint32_t)(p * 16 * 2);
                uint32_t r0, r1, r2, r3;
                LDSM_X4_T(r0, r1, r2, r3, vhB + off);
                VfH[2 * p][0] = r0; VfH[2 * p][1] = r1;
                VfH[2 * p + 1][0] = r2; VfH[2 * p + 1][1] = r3;
            }
#pragma unroll
            for (int nt = 0; nt < 8; nt++)
                MMA_F16(O[nt], Pah[kt], VfH[nt]);
        }
    }

    // ---- epilogue: normalize, split, write ctx fp16 planes ----
    float inv0 = 1.0f / l0, inv1 = 1.0f / l1;
    int b = bh >> 4, h = bh & 15;
    int r0g = q0 + w * 16 + gid;
    int r1g = r0g + 8;
#pragma unroll
    for (int nt = 0; nt < 8; nt++) {
        int d = nt * 8 + 2 * tig;
        size_t p0 = (size_t)(b * SEQ + r0g) * 512 + ((h * 64 + d) >> 1);
        size_t p1 = (size_t)(b * SEQ + r1g) * 512 + ((h * 64 + d) >> 1);
        float v0 = O[nt][0] * inv0, v1 = O[nt][1] * inv0;
        uint32_t hi = h2pack(v0, v1);
        g_ch[p0] = hi;
        g_cl[p0] = h2pack(v0 - h_lo(hi), v1 - h_hi(hi));
        v0 = O[nt][2] * inv1; v1 = O[nt][3] * inv1;
        hi = h2pack(v0, v1);
        g_ch[p1] = hi;
        g_cl[p1] = h2pack(v0 - h_lo(hi), v1 - h_hi(hi));
    }
}

// ---------------------------------------------------------------------------
extern "C" void kernel_launch(void* const* d_in, const int* in_sizes, int n_in,
                              void* d_out, int out_size)
{
    const float* query = (const float*)d_in[0];   // [4,2048,1024]
    const float* in_w  = (const float*)d_in[1];   // [3072,1024]
    const float* in_b  = (const float*)d_in[2];   // [3072]
    const float* out_w = (const float*)d_in[3];   // [1024,1024]
    const float* out_b = (const float*)d_in[4];   // [1024]
    float* out = (float*)d_out;                   // [4,2048,1024]

    cudaFuncSetAttribute(gemm_v2,
                         cudaFuncAttributeMaxDynamicSharedMemorySize, GEMM_SMEM2);
    cudaFuncSetAttribute(attn_v2,
                         cudaFuncAttributeMaxDynamicSharedMemorySize, ATTN_SMEM2);

    // 0) one-pass fp32 -> fp16 plane splits
    conv_split<<<(M_ROWS * E_DIM / 4) / 256, 256>>>((const float4*)query, 0,
                                                    M_ROWS * E_DIM / 4);
    conv_split<<<(3 * E_DIM * E_DIM / 4) / 256, 256>>>((const float4*)in_w, 1,
                                                       3 * E_DIM * E_DIM / 4);
    conv_split<<<(E_DIM * E_DIM / 4) / 256, 256>>>((const float4*)out_w, 2,
                                                   E_DIM * E_DIM / 4);

    // 1) QKV projection + scatter (q scaled w/ log2e)
    gemm_v2<<<dim3(3 * E_DIM / 128, M_ROWS / 128), 256, GEMM_SMEM2>>>(
        in_b, nullptr, E_DIM, 3 * E_DIM, 0);

    // 2) Tensor-core flash attention -> ctx fp16 planes (2 CTAs/SM)
    attn_v2<<<dim3(SEQ / 128, BH_TOT), 256, ATTN_SMEM2>>>();

    // 3) Output projection -> d_out (fp32)
    gemm_v2<<<dim3(E_DIM / 128, M_ROWS / 128), 256, GEMM_SMEM2>>>(
        out_b, out, E_DIM, E_DIM, 1);
}